// round 13
// baseline (speedup 1.0000x reference)
#include <cuda_runtime.h>
#include <cuda_fp16.h>
#include <cstdint>

#define NB 4
#define HH 128
#define WWD 128
#define CC 256
#define NDIL 16
#define DF 8
#define CATC 384
#define HW (HH*WWD)
#define NPIX (NB*HW)
#define EPSF 1e-3f

// ---------------- scratch ----------------
__device__ float g_x32[(size_t)NPIX*CC];
__device__ __half g_hf[(size_t)NPIX*CATC];
__device__ float g_dx [(size_t)NDIL*NPIX*DF];
__device__ float g_kq [(size_t)NDIL*NB*DF*HW];
__device__ float g_v  [(size_t)NDIL*NPIX*DF];
__device__ float g_pre[(size_t)NPIX*CC];
__device__ float g_smax[NDIL*NB*DF];
__device__ float g_sinv[NDIL*NB*DF];
__device__ __half g_Wh[(size_t)9*256*384];

// ---------------- stream kit ----------------
namespace {
struct StreamKit {
    cudaStream_t s1;
    cudaEvent_t eFork, eW, eL, eChain;
    StreamKit(){
        int lo = 0, hi = 0;
        cudaDeviceGetStreamPriorityRange(&lo, &hi);
        cudaStreamCreateWithPriority(&s1, cudaStreamNonBlocking, hi);
        cudaEventCreateWithFlags(&eFork,  cudaEventDisableTiming);
        cudaEventCreateWithFlags(&eW,     cudaEventDisableTiming);
        cudaEventCreateWithFlags(&eL,     cudaEventDisableTiming);
        cudaEventCreateWithFlags(&eChain, cudaEventDisableTiming);
    }
};
StreamKit g_sk;
}

// ---------------- f32x2 helpers ----------------
__device__ __forceinline__ unsigned long long dup2(float f){
    unsigned long long r; unsigned u = __float_as_uint(f);
    asm("mov.b64 %0, {%1, %1};" : "=l"(r) : "r"(u));
    return r;
}
__device__ __forceinline__ unsigned long long ffma2(unsigned long long a, unsigned long long b, unsigned long long c){
    unsigned long long d;
    asm("fma.rn.f32x2 %0, %1, %2, %3;" : "=l"(d) : "l"(a), "l"(b), "l"(c));
    return d;
}
__device__ __forceinline__ float2 unpk(unsigned long long v){
    unsigned lo, hi;
    asm("mov.b64 {%0, %1}, %2;" : "=r"(lo), "=r"(hi) : "l"(v));
    return make_float2(__uint_as_float(lo), __uint_as_float(hi));
}

// ---------------- warp MMA + cp.async plumbing ----------------
__device__ __forceinline__ uint32_t smem_u32(const void* p){
    uint32_t a;
    asm("{ .reg .u64 t; cvta.to.shared.u64 t, %1; cvt.u32.u64 %0, t; }" : "=r"(a) : "l"(p));
    return a;
}
__device__ __forceinline__ void ldsm4(uint32_t* r, uint32_t addr){
    asm volatile("ldmatrix.sync.aligned.m8n8.x4.shared.b16 {%0,%1,%2,%3}, [%4];"
        : "=r"(r[0]), "=r"(r[1]), "=r"(r[2]), "=r"(r[3]) : "r"(addr));
}
__device__ __forceinline__ void mma16816h(float* c, const uint32_t* a, const uint32_t* b){
    asm volatile("mma.sync.aligned.m16n8k16.row.col.f32.f16.f16.f32 "
        "{%0,%1,%2,%3}, {%4,%5,%6,%7}, {%8,%9}, {%0,%1,%2,%3};"
        : "+f"(c[0]), "+f"(c[1]), "+f"(c[2]), "+f"(c[3])
        : "r"(a[0]), "r"(a[1]), "r"(a[2]), "r"(a[3]), "r"(b[0]), "r"(b[1]));
}
__device__ __forceinline__ void cpa16(uint32_t dst, const void* src, uint32_t srcsize){
    asm volatile("cp.async.cg.shared.global [%0], [%1], 16, %2;"
        :: "r"(dst), "l"(src), "r"(srcsize) : "memory");
}
#define CP_COMMIT() asm volatile("cp.async.commit_group;" ::: "memory")
#define CP_WAIT1()  asm volatile("cp.async.wait_group 1;" ::: "memory")
#define CP_WAIT0()  asm volatile("cp.async.wait_group 0;" ::: "memory")

__device__ __forceinline__ void store_h8(__half* hp, const float* v){
    __half hh[8];
    #pragma unroll
    for (int j=0;j<8;j++) hh[j] = __float2half_rn(v[j]);
    *(uint4*)hp = *(uint4*)hh;
}

// ---------------- K0: weight prep ----------------
__global__ __launch_bounds__(256) void k_wprep(const float* __restrict__ W){
    int idx = blockIdx.x*256 + threadIdx.x;
    int oc = idx & 255;
    int rest = idx >> 8;
    int ch = rest % 384, tap = rest / 384;
    float w = W[idx];
    size_t o = ((size_t)(tap*256 + oc))*384 + ch;
    g_Wh[o] = __float2half_rn(w);
}

// ---------------- K1: input LayerNorm ----------------
__global__ __launch_bounds__(256) void k_ln_in(const float* __restrict__ x,
                                               const float* __restrict__ gg, const float* __restrict__ bb){
    int gw = (blockIdx.x*blockDim.x + threadIdx.x) >> 5;
    int lane = threadIdx.x & 31;
    if (gw >= NPIX) return;
    const float4* sp = (const float4*)(x + (size_t)gw*CC);
    float4 a0 = sp[lane*2], a1 = sp[lane*2+1];
    float s = a0.x+a0.y+a0.z+a0.w + a1.x+a1.y+a1.z+a1.w;
    #pragma unroll
    for (int o=16;o;o>>=1) s += __shfl_xor_sync(0xffffffffu, s, o);
    float m = s * (1.0f/256.0f);
    float d[8] = {a0.x-m,a0.y-m,a0.z-m,a0.w-m,a1.x-m,a1.y-m,a1.z-m,a1.w-m};
    float q = 0.f;
    #pragma unroll
    for (int j=0;j<8;j++) q += d[j]*d[j];
    #pragma unroll
    for (int o=16;o;o>>=1) q += __shfl_xor_sync(0xffffffffu, q, o);
    float r = rsqrtf(q*(1.0f/256.0f) + EPSF);
    const float4* gp = (const float4*)gg; const float4* bp = (const float4*)bb;
    float4 g0 = gp[lane*2], g1 = gp[lane*2+1];
    float4 b0 = bp[lane*2], b1 = bp[lane*2+1];
    float gv[8] = {g0.x,g0.y,g0.z,g0.w,g1.x,g1.y,g1.z,g1.w};
    float bv[8] = {b0.x,b0.y,b0.z,b0.w,b1.x,b1.y,b1.z,b1.w};
    float o[8];
    #pragma unroll
    for (int j=0;j<8;j++) o[j] = d[j]*r*gv[j] + bv[j];
    float* dp = g_x32 + (size_t)gw*CC + lane*8;
    *(float4*)dp = make_float4(o[0],o[1],o[2],o[3]);
    *(float4*)(dp+4) = make_float4(o[4],o[5],o[6],o[7]);
    store_h8(g_hf + (size_t)gw*CATC + lane*8, o);
}

// ---------------- K2: 1x1 down conv (256 -> 8), 2 branches per CTA, relu, f32x2 ----------------
__global__ __launch_bounds__(256) void k_dwn(const float* __restrict__ Wd, const float* __restrict__ Bd){
    __shared__ __align__(16) float ws[2*CC*DF];
    __shared__ float xs[8][1024];
    const int i0 = blockIdx.x * 2;
    const int px0 = blockIdx.y * 1024;
    const int t = threadIdx.x;

    const float4* wsrc = (const float4*)(Wd + (size_t)i0*CC*DF);
    for (int idx = t; idx < 2*CC*DF/4; idx += 256) ((float4*)ws)[idx] = wsrc[idx];

    unsigned long long acc[2][4][4];
    #pragma unroll
    for (int br=0;br<2;br++)
        #pragma unroll
        for (int j=0;j<4;j++)
            #pragma unroll
            for (int k=0;k<4;k++) acc[br][j][k] = 0ull;

    for (int cc = 0; cc < CC; cc += 8){
        __syncthreads();
        #pragma unroll
        for (int j = 0; j < 4; j++){
            int p = t + 256*j;
            const float* src = g_x32 + (size_t)(px0 + p)*CC + cc;
            float4 v0 = *(const float4*)src;
            float4 v1 = *(const float4*)(src+4);
            xs[0][p]=v0.x; xs[1][p]=v0.y; xs[2][p]=v0.z; xs[3][p]=v0.w;
            xs[4][p]=v1.x; xs[5][p]=v1.y; xs[6][p]=v1.z; xs[7][p]=v1.w;
        }
        __syncthreads();
        #pragma unroll
        for (int c = 0; c < 8; c++){
            unsigned long long xd0 = dup2(xs[c][t]),     xd1 = dup2(xs[c][t+256]);
            unsigned long long xd2 = dup2(xs[c][t+512]), xd3 = dup2(xs[c][t+768]);
            #pragma unroll
            for (int br = 0; br < 2; br++){
                const unsigned long long* wp = (const unsigned long long*)&ws[br*CC*DF + (cc+c)*8];
                unsigned long long w0=wp[0], w1=wp[1], w2=wp[2], w3=wp[3];
                acc[br][0][0]=ffma2(xd0,w0,acc[br][0][0]); acc[br][0][1]=ffma2(xd0,w1,acc[br][0][1]);
                acc[br][0][2]=ffma2(xd0,w2,acc[br][0][2]); acc[br][0][3]=ffma2(xd0,w3,acc[br][0][3]);
                acc[br][1][0]=ffma2(xd1,w0,acc[br][1][0]); acc[br][1][1]=ffma2(xd1,w1,acc[br][1][1]);
                acc[br][1][2]=ffma2(xd1,w2,acc[br][1][2]); acc[br][1][3]=ffma2(xd1,w3,acc[br][1][3]);
                acc[br][2][0]=ffma2(xd2,w0,acc[br][2][0]); acc[br][2][1]=ffma2(xd2,w1,acc[br][2][1]);
                acc[br][2][2]=ffma2(xd2,w2,acc[br][2][2]); acc[br][2][3]=ffma2(xd2,w3,acc[br][2][3]);
                acc[br][3][0]=ffma2(xd3,w0,acc[br][3][0]); acc[br][3][1]=ffma2(xd3,w1,acc[br][3][1]);
                acc[br][3][2]=ffma2(xd3,w2,acc[br][3][2]); acc[br][3][3]=ffma2(xd3,w3,acc[br][3][3]);
            }
        }
    }
    #pragma unroll
    for (int br = 0; br < 2; br++){
        float bb[8];
        #pragma unroll
        for (int oc=0;oc<8;oc++) bb[oc] = Bd[(i0+br)*8+oc];
        #pragma unroll
        for (int j=0;j<4;j++){
            int p = px0 + t + 256*j;
            float o[8];
            #pragma unroll
            for (int k=0;k<4;k++){
                float2 f = unpk(acc[br][j][k]);
                o[2*k]   = fmaxf(f.x + bb[2*k],   0.f);
                o[2*k+1] = fmaxf(f.y + bb[2*k+1], 0.f);
            }
            float* dp = g_dx + ((size_t)(i0+br)*NPIX + p)*DF;
            *(float4*)dp     = make_float4(o[0],o[1],o[2],o[3]);
            *(float4*)(dp+4) = make_float4(o[4],o[5],o[6],o[7]);
        }
    }
}

// ---------------- K3: k,q,v 3x3 dilated convs + relu + kq product ----------------
__global__ __launch_bounds__(64) void k_kqv(const float* __restrict__ Kw, const float* __restrict__ Kb,
                                            const float* __restrict__ Qw, const float* __restrict__ Qb,
                                            const float* __restrict__ Vw, const float* __restrict__ Vb){
    __shared__ float xs[3][8][128];
    __shared__ float wsk[576], wsq[576], wsv[576];
    __shared__ float sbk[8], sbq[8], sbv[8];

    const int h = blockIdx.x, n = blockIdx.y, i = blockIdx.z;
    const int d = i + 1;
    const int t = threadIdx.x;

    const float* dxb = g_dx + ((size_t)i*NPIX + (size_t)n*HW)*DF;
    #pragma unroll
    for (int r = 0; r < 3; r++){
        int hh = h + (r-1)*d;
        if ((unsigned)hh < (unsigned)HH){
            #pragma unroll
            for (int j = 0; j < 2; j++){
                int w = t + 64*j;
                const float* src = dxb + (size_t)(hh*WWD + w)*DF;
                float4 v0 = *(const float4*)src;
                float4 v1 = *(const float4*)(src+4);
                xs[r][0][w]=v0.x; xs[r][1][w]=v0.y; xs[r][2][w]=v0.z; xs[r][3][w]=v0.w;
                xs[r][4][w]=v1.x; xs[r][5][w]=v1.y; xs[r][6][w]=v1.z; xs[r][7][w]=v1.w;
            }
        } else {
            for (int idx = t; idx < 8*128; idx += 64) (&xs[r][0][0])[idx] = 0.f;
        }
    }
    for (int idx = t; idx < 576; idx += 64){
        wsk[idx] = Kw[(size_t)i*576 + idx];
        wsq[idx] = Qw[(size_t)i*576 + idx];
        wsv[idx] = Vw[(size_t)i*576 + idx];
    }
    if (t < 8){ sbk[t]=Kb[i*8+t]; sbq[t]=Qb[i*8+t]; sbv[t]=Vb[i*8+t]; }
    __syncthreads();

    const int w0 = t, w1 = t + 64;
    float ak0[8], ak1[8], aq0[8], aq1[8], av0[8], av1[8];
    #pragma unroll
    for (int c=0;c<8;c++){ ak0[c]=ak1[c]=aq0[c]=aq1[c]=av0[c]=av1[c]=0.f; }

    #pragma unroll 1
    for (int tap = 0; tap < 9; tap++){
        int ky = tap/3, kx = tap%3;
        int c0 = w0 + (kx-1)*d; bool ok0 = (unsigned)c0 < (unsigned)WWD;
        int c1 = w1 + (kx-1)*d; bool ok1 = (unsigned)c1 < (unsigned)WWD;
        const float* xr = &xs[ky][0][0];
        #pragma unroll
        for (int ci = 0; ci < 8; ci++){
            float x0 = ok0 ? xr[ci*128 + c0] : 0.f;
            float x1 = ok1 ? xr[ci*128 + c1] : 0.f;
            const float* wk = &wsk[(tap*8+ci)*8];
            const float* wq = &wsq[(tap*8+ci)*8];
            const float* wv = &wsv[(tap*8+ci)*8];
            #pragma unroll
            for (int co = 0; co < 8; co++){
                ak0[co] += x0*wk[co]; ak1[co] += x1*wk[co];
                aq0[co] += x0*wq[co]; aq1[co] += x1*wq[co];
                av0[co] += x0*wv[co]; av1[co] += x1*wv[co];
            }
        }
    }

    float kq0[8], kq1[8], vv0[8], vv1[8];
    #pragma unroll
    for (int co = 0; co < 8; co++){
        float k0 = fmaxf(ak0[co]+sbk[co],0.f), k1 = fmaxf(ak1[co]+sbk[co],0.f);
        float q0 = fmaxf(aq0[co]+sbq[co],0.f), q1 = fmaxf(aq1[co]+sbq[co],0.f);
        vv0[co]  = fmaxf(av0[co]+sbv[co],0.f); vv1[co] = fmaxf(av1[co]+sbv[co],0.f);
        kq0[co] = k0*q0; kq1[co] = k1*q1;
    }
    const int in = i*NB + n;
    const int hwb = h*WWD;
    #pragma unroll
    for (int co = 0; co < 8; co++){
        float* kp = g_kq + ((size_t)in*DF + co)*HW + hwb;
        kp[w0] = kq0[co]; kp[w1] = kq1[co];
    }
    float* vp0 = g_v + ((size_t)i*NPIX + (size_t)n*HW + hwb + w0)*DF;
    float* vp1 = g_v + ((size_t)i*NPIX + (size_t)n*HW + hwb + w1)*DF;
    *(float4*)vp0     = make_float4(vv0[0],vv0[1],vv0[2],vv0[3]);
    *(float4*)(vp0+4) = make_float4(vv0[4],vv0[5],vv0[6],vv0[7]);
    *(float4*)vp1     = make_float4(vv1[0],vv1[1],vv1[2],vv1[3]);
    *(float4*)(vp1+4) = make_float4(vv1[4],vv1[5],vv1[6],vv1[7]);
}

// ---------------- K4: softmax stats ----------------
__global__ __launch_bounds__(256) void k_softstats(){
    const int plane = blockIdx.x;
    const float4* p = (const float4*)(g_kq + (size_t)plane*HW);
    const int t = threadIdx.x, lane = t & 31, warp = t >> 5;
    __shared__ float red[8];

    float m = -1e30f;
    for (int idx = t; idx < HW/4; idx += 256){
        float4 v = p[idx];
        m = fmaxf(m, fmaxf(fmaxf(v.x,v.y), fmaxf(v.z,v.w)));
    }
    #pragma unroll
    for (int o=16;o;o>>=1) m = fmaxf(m, __shfl_xor_sync(0xffffffffu, m, o));
    if (lane==0) red[warp] = m;
    __syncthreads();
    float bm = red[0];
    #pragma unroll
    for (int k=1;k<8;k++) bm = fmaxf(bm, red[k]);
    __syncthreads();

    float s = 0.f;
    for (int idx = t; idx < HW/4; idx += 256){
        float4 v = p[idx];
        s += __expf(v.x-bm) + __expf(v.y-bm) + __expf(v.z-bm) + __expf(v.w-bm);
    }
    #pragma unroll
    for (int o=16;o;o>>=1) s += __shfl_xor_sync(0xffffffffu, s, o);
    if (lane==0) red[warp] = s;
    __syncthreads();
    if (t == 0){
        float tot = 0.f;
        #pragma unroll
        for (int k=0;k<8;k++) tot += red[k];
        g_smax[plane] = bm;
        g_sinv[plane] = 1.0f / tot;
    }
}

// ---------------- K5: softmax*v + LN over DF -> fp16 cat channels ----------------
__global__ __launch_bounds__(256) void k_attn_ln(const float* __restrict__ gup, const float* __restrict__ bup){
    __shared__ float sm[8], si[8], sg[8], sb[8];
    const int in = blockIdx.y;
    const int t = threadIdx.x;
    if (t < 8){ sm[t]=g_smax[in*DF+t]; si[t]=g_sinv[in*DF+t]; sg[t]=gup[t]; sb[t]=bup[t]; }
    __syncthreads();
    const int hw = blockIdx.x*256 + t;
    const int i = in >> 2, n = in & 3;

    size_t vb = ((size_t)i*NPIX + (size_t)n*HW + hw)*DF;
    float4 v0 = *(const float4*)&g_v[vb];
    float4 v1 = *(const float4*)&g_v[vb+4];
    float vv[8] = {v0.x,v0.y,v0.z,v0.w,v1.x,v1.y,v1.z,v1.w};

    float y[8]; float s = 0.f;
    #pragma unroll
    for (int c = 0; c < 8; c++){
        float kq = g_kq[((size_t)in*DF + c)*HW + hw];
        float a = __expf(kq - sm[c]) * si[c];
        y[c] = a * vv[c];
        s += y[c];
    }
    float mean = s * 0.125f, q = 0.f;
    #pragma unroll
    for (int c = 0; c < 8; c++){ float dd = y[c]-mean; q += dd*dd; }
    float r = rsqrtf(q*0.125f + EPSF);
    float o[8];
    #pragma unroll
    for (int c = 0; c < 8; c++) o[c] = (y[c]-mean)*r*sg[c] + sb[c];

    size_t ob = ((size_t)(n*HW + hw))*CATC + CC + i*DF;
    store_h8(g_hf + ob, o);
}

// ---------------- K6a: smooth conv part1 (xn channels), HMMA fp16, 3-buffer ring ----------------
#define BUF_BYTES 32768
#define K6_SMEM (1024 + 3*BUF_BYTES)

__global__ void __launch_bounds__(256, 2) k_smooth_p1(){
    extern __shared__ __align__(128) char smem[];
    const uint32_t sb0 = smem_u32(smem) + 1024;

    const int t = threadIdx.x;
    const int lane = t & 31, wid = t >> 5;
    const int wm = wid & 3, wn = wid >> 2;
    const int row_id = blockIdx.x;
    const int n = row_id >> 7, h = row_id & 127;
    const int oc0 = blockIdx.y * 128;

    const int srow = t >> 1;
    const int cb   = (t & 1) * 4;

    uint32_t dsw[4];
    #pragma unroll
    for (int j = 0; j < 4; j++){
        uint32_t off = (uint32_t)srow*128 + (uint32_t)(cb + j)*16;
        dsw[j] = off ^ ((off >> 3) & 0x70);
    }

    auto stage_issue = [&](int s, int b){
        const int tap = s / 4, cc = (s % 4) * 64;
        const int dy = tap/3 - 1, dxo = tap%3 - 1;
        const int hh = h + dy;
        const int ww = srow + dxo;
        const bool ok = ((unsigned)hh < (unsigned)HH) && ((unsigned)ww < (unsigned)WWD);
        const int hcl = ok ? hh : 0, wcl = ok ? ww : 0;
        const uint32_t sz = ok ? 16u : 0u;
        const uint32_t base = sb0 + (uint32_t)b*BUF_BYTES;
        const size_t abase = ((size_t)((n*HH + hcl)*WWD + wcl))*CATC + cc + cb*8;
        const size_t wbase = ((size_t)(tap*256 + oc0 + srow))*CATC + cc + cb*8;
        #pragma unroll
        for (int j = 0; j < 4; j++){
            cpa16(base +         dsw[j], g_hf + abase + j*8, sz);
            cpa16(base + 16384 + dsw[j], g_Wh + wbase + j*8, 16u);
        }
        CP_COMMIT();
    };

    const int pix0 = row_id * 128;
    float acc[2][8][4];
    #pragma unroll
    for (int a=0;a<2;a++)
        #pragma unroll
        for (int b=0;b<8;b++)
            #pragma unroll
            for (int c=0;c<4;c++) acc[a][b][c] = 0.f;

    stage_issue(0, 0);

    int bnext = 1;
    #pragma unroll 1
    for (int s = 0; s < 36; s++){
        if (s + 1 < 36){
            stage_issue(s + 1, bnext);
            if (++bnext == 3) bnext = 0;
            CP_WAIT1();
        } else {
            CP_WAIT0();
        }
        __syncthreads();

        int bcur = s % 3;
        const uint32_t base = sb0 + (uint32_t)bcur*BUF_BYTES;
        const uint32_t aB = base, bB = base + 16384;

        #pragma unroll
        for (int ks = 0; ks < 4; ks++){
            uint32_t ah[2][4];
            #pragma unroll
            for (int mt = 0; mt < 2; mt++){
                uint32_t arow = (uint32_t)(wm*32 + mt*16 + (lane & 15));
                uint32_t ac16 = (uint32_t)(ks*2 + (lane >> 4));
                uint32_t off = arow*128 + ac16*16;
                uint32_t sw = off ^ ((off >> 3) & 0x70);
                ldsm4(ah[mt], aB + sw);
            }
            uint32_t brow = (uint32_t)(wn*64 + ((lane >> 4) << 3) + (lane & 7));
            uint32_t bc16 = (uint32_t)(ks*2 + ((lane >> 3) & 1));
            #pragma unroll
            for (int g = 0; g < 4; g++){
                uint32_t off = (brow + (uint32_t)g*16)*128 + bc16*16;
                uint32_t sw = off ^ ((off >> 3) & 0x70);
                uint32_t bfr[4];
                ldsm4(bfr, bB + sw);
                mma16816h(acc[0][2*g],   ah[0], bfr);
                mma16816h(acc[1][2*g],   ah[1], bfr);
                mma16816h(acc[0][2*g+1], ah[0], bfr+2);
                mma16816h(acc[1][2*g+1], ah[1], bfr+2);
            }
        }
    }

    #pragma unroll
    for (int mt = 0; mt < 2; mt++){
        #pragma unroll
        for (int nt = 0; nt < 8; nt++){
            int r = wm*32 + mt*16 + (lane >> 2);
            int cidx = wn*64 + nt*8 + (lane & 3)*2;
            float* p0 = g_pre + (size_t)(pix0 + r)*CC + oc0 + cidx;
            float* p1 = g_pre + (size_t)(pix0 + r + 8)*CC + oc0 + cidx;
            *(float2*)p0 = make_float2(acc[mt][nt][0], acc[mt][nt][1]);
            *(float2*)p1 = make_float2(acc[mt][nt][2], acc[mt][nt][3]);
        }
    }
}

// ---------------- K6b: part2 (attn ch) + bias + relu + fused LN, M=64 x N=256, 2 CTAs/SM ----------------
// grid 1024 (half-row per CTA), 256 threads = 8 warps: wm=wid&1 (m32), wn=wid>>1 (n64 of 256).
#define P2F_BUF 40960
#define P2F_SMEM (5120 + 2*P2F_BUF)

__global__ void __launch_bounds__(256, 2) k_smooth_p2f(const float* __restrict__ bias,
                                                       const float* __restrict__ gout,
                                                       const float* __restrict__ bout,
                                                       float* __restrict__ out){
    extern __shared__ __align__(128) char smem[];
    float* s_bias = (float*)smem;               // 256 f
    float* s_g    = (float*)(smem + 1024);      // 256 f
    float* s_b    = (float*)(smem + 2048);      // 256 f
    float* s_red  = (float*)(smem + 3072);      // [64 rows][4 wn][2] = 2 KB
    const uint32_t sb0 = smem_u32(smem) + 5120;

    const int t = threadIdx.x;
    const int lane = t & 31, wid = t >> 5;
    const int wm = wid & 1, wn = wid >> 1;      // wm 0..1, wn 0..3
    const int bid = blockIdx.x;
    const int n = bid >> 8, h = (bid >> 1) & 127, w0 = (bid & 1) * 64;
    const int pix0 = bid * 64;

    if (t < 256){ s_bias[t] = bias[t]; s_g[t] = gout[t]; s_b[t] = bout[t]; }

    // staging: A = 64 rows x 8 chunks (2/thread), B = 256 rows x 8 chunks (8/thread, 1 row/thread)
    const int srowA = t >> 2, cbA = (t & 3) * 2;
    const int srowB = t;
    uint32_t dswA[2], dswB[8];
    #pragma unroll
    for (int j = 0; j < 2; j++){
        uint32_t off = (uint32_t)srowA*128 + (uint32_t)(cbA + j)*16;
        dswA[j] = off ^ ((off >> 3) & 0x70);
    }
    #pragma unroll
    for (int j = 0; j < 8; j++){
        uint32_t off = (uint32_t)srowB*128 + (uint32_t)j*16;
        dswB[j] = off ^ ((off >> 3) & 0x70);
    }

    auto stage_issue = [&](int s, int b){
        const int tap = s / 2, cc = 256 + (s % 2) * 64;
        const int dy = tap/3 - 1, dxo = tap%3 - 1;
        const int hh = h + dy;
        const int ww = w0 + srowA + dxo;
        const bool ok = ((unsigned)hh < (unsigned)HH) && ((unsigned)ww < (unsigned)WWD);
        const int hcl = ok ? hh : 0, wcl = ok ? ww : 0;
        const uint32_t sz = ok ? 16u : 0u;
        const uint32_t base = sb0 + (uint32_t)b*P2F_BUF;
        const size_t abase = ((size_t)((n*HH + hcl)*WWD + wcl))*CATC + cc + cbA*8;
        const size_t wbase = ((size_t)(tap*256 + srowB))*CATC + cc;
        #pragma unroll
        for (int j = 0; j < 2; j++)
            cpa16(base + dswA[j], g_hf + abase + j*8, sz);
        #pragma unroll
        for (int j = 0; j < 8; j++)
            cpa16(base + 8192 + dswB[j], g_Wh + wbase + j*8, 16u);
        CP_COMMIT();
    };

    // init acc from part1 partials
    float acc[2][8][4];
    #pragma unroll
    for (int mt = 0; mt < 2; mt++){
        #pragma unroll
        for (int nt = 0; nt < 8; nt++){
            int r = wm*32 + mt*16 + (lane >> 2);
            int cidx = wn*64 + nt*8 + (lane & 3)*2;
            float2 v0 = *(const float2*)(g_pre + (size_t)(pix0 + r)*CC + cidx);
            float2 v1 = *(const float2*)(g_pre + (size_t)(pix0 + r + 8)*CC + cidx);
            acc[mt][nt][0]=v0.x; acc[mt][nt][1]=v0.y; acc[mt][nt][2]=v1.x; acc[mt][nt][3]=v1.y;
        }
    }

    stage_issue(0, 0);

    #pragma unroll 1
    for (int s = 0; s < 18; s++){
        if (s + 1 < 18){
            stage_issue(s + 1, (s + 1) & 1);
            CP_WAIT1();
        } else {
            CP_WAIT0();
        }
        __syncthreads();

        const uint32_t base = sb0 + (uint32_t)(s & 1)*P2F_BUF;
        const uint32_t aB = base, bB = base + 8192;

        #pragma unroll
        for (int ks = 0; ks < 4; ks++){
            uint32_t ah[2][4];
            #pragma unroll
            for (int mt = 0; mt < 2; mt++){
                uint32_t arow = (uint32_t)(wm*32 + mt*16 + (lane & 15));
                uint32_t ac16 = (uint32_t)(ks*2 + (lane >> 4));
                uint32_t off = arow*128 + ac16*16;
                uint32_t sw = off ^ ((off >> 3) & 0x70);
                ldsm4(ah[mt], aB + sw);
            }
            uint32_t brow = (uint32_t)(wn*64 + ((lane >> 4) << 3) + (lane & 7));
            uint32_t bc16 = (uint32_t)(ks*2 + ((lane >> 3) & 1));
            #pragma unroll
            for (int g = 0; g < 4; g++){
                uint32_t off = (brow + (uint32_t)g*16)*128 + bc16*16;
                uint32_t sw = off ^ ((off >> 3) & 0x70);
                uint32_t bfr[4];
                ldsm4(bfr, bB + sw);
                mma16816h(acc[0][2*g],   ah[0], bfr);
                mma16816h(acc[1][2*g],   ah[1], bfr);
                mma16816h(acc[0][2*g+1], ah[0], bfr+2);
                mma16816h(acc[1][2*g+1], ah[1], bfr+2);
            }
        }
        __syncthreads();
    }

    // ---- epilogue: bias + relu, fused LayerNorm over 256 channels (64 rows per CTA) ----
    float sr[4], qr[4];
    #pragma unroll
    for (int m = 0; m < 4; m++){ sr[m] = 0.f; qr[m] = 0.f; }
    #pragma unroll
    for (int mt = 0; mt < 2; mt++){
        #pragma unroll
        for (int nt = 0; nt < 8; nt++){
            int cidx = wn*64 + nt*8 + (lane & 3)*2;
            float b0 = s_bias[cidx], b1 = s_bias[cidx+1];
            float v0 = fmaxf(acc[mt][nt][0] + b0, 0.f);
            float v1 = fmaxf(acc[mt][nt][1] + b1, 0.f);
            float v2 = fmaxf(acc[mt][nt][2] + b0, 0.f);
            float v3 = fmaxf(acc[mt][nt][3] + b1, 0.f);
            acc[mt][nt][0]=v0; acc[mt][nt][1]=v1; acc[mt][nt][2]=v2; acc[mt][nt][3]=v3;
            sr[mt*2+0] += v0 + v1;  qr[mt*2+0] += v0*v0 + v1*v1;
            sr[mt*2+1] += v2 + v3;  qr[mt*2+1] += v2*v2 + v3*v3;
        }
    }
    #pragma unroll
    for (int m = 0; m < 4; m++){
        #pragma unroll
        for (int o = 1; o <= 2; o <<= 1){
            sr[m] += __shfl_xor_sync(0xffffffffu, sr[m], o);
            qr[m] += __shfl_xor_sync(0xffffffffu, qr[m], o);
        }
    }
    if ((lane & 3) == 0){
        #pragma unroll
        for (int m = 0; m < 4; m++){
            int row = wm*32 + (m>>1)*16 + (lane >> 2) + (m&1)*8;
            s_red[(row*4 + wn)*2 + 0] = sr[m];
            s_red[(row*4 + wn)*2 + 1] = qr[m];
        }
    }
    __syncthreads();

    float mean[4], rinv[4];
    #pragma unroll
    for (int m = 0; m < 4; m++){
        int row = wm*32 + (m>>1)*16 + (lane >> 2) + (m&1)*8;
        float ts = 0.f, tq = 0.f;
        #pragma unroll
        for (int w = 0; w < 4; w++){
            ts += s_red[(row*4 + w)*2 + 0];
            tq += s_red[(row*4 + w)*2 + 1];
        }
        float mu = ts * (1.0f/256.0f);
        float var = fmaxf(tq * (1.0f/256.0f) - mu*mu, 0.f);
        mean[m] = mu;
        rinv[m] = rsqrtf(var + EPSF);
    }

    #pragma unroll
    for (int mt = 0; mt < 2; mt++){
        #pragma unroll
        for (int nt = 0; nt < 8; nt++){
            int r = wm*32 + mt*16 + (lane >> 2);
            int cidx = wn*64 + nt*8 + (lane & 3)*2;
            float g0 = s_g[cidx], g1 = s_g[cidx+1];
            float o0 = s_b[cidx], o1 = s_b[cidx+1];
            int m0 = mt*2, m1 = mt*2 + 1;
            float* p0 = out + (size_t)(pix0 + r)*CC + cidx;
            float* p1 = out + (size_t)(pix0 + r + 8)*CC + cidx;
            *(float2*)p0 = make_float2((acc[mt][nt][0]-mean[m0])*rinv[m0]*g0 + o0,
                                       (acc[mt][nt][1]-mean[m0])*rinv[m0]*g1 + o1);
            *(float2*)p1 = make_float2((acc[mt][nt][2]-mean[m1])*rinv[m1]*g0 + o0,
                                       (acc[mt][nt][3]-mean[m1])*rinv[m1]*g1 + o1);
        }
    }
}

// ---------------- launch ----------------
extern "C" void kernel_launch(void* const* d_in, const int* in_sizes, int n_in,
                              void* d_out, int out_size){
    (void)in_sizes; (void)n_in; (void)out_size;
    const float* x        = (const float*)d_in[0];
    const float* dwn_w    = (const float*)d_in[1];
    const float* dwn_b    = (const float*)d_in[2];
    const float* k_w      = (const float*)d_in[3];
    const float* k_b      = (const float*)d_in[4];
    const float* q_w      = (const float*)d_in[5];
    const float* q_b      = (const float*)d_in[6];
    const float* v_w      = (const float*)d_in[7];
    const float* v_b      = (const float*)d_in[8];
    const float* smooth_w = (const float*)d_in[9];
    const float* smooth_b = (const float*)d_in[10];
    const float* ln_in_g  = (const float*)d_in[11];
    const float* ln_in_b  = (const float*)d_in[12];
    const float* ln_up_g  = (const float*)d_in[13];
    const float* ln_up_b  = (const float*)d_in[14];
    const float* ln_out_g = (const float*)d_in[15];
    const float* ln_out_b = (const float*)d_in[16];
    float* out = (float*)d_out;

    cudaFuncSetAttribute(k_smooth_p1,  cudaFuncAttributeMaxDynamicSharedMemorySize, K6_SMEM);
    cudaFuncSetAttribute(k_smooth_p2f, cudaFuncAttributeMaxDynamicSharedMemorySize, P2F_SMEM);

    // fork: s1 joins capture via event recorded on origin stream first
    cudaEventRecord(g_sk.eFork, 0);
    cudaStreamWaitEvent(g_sk.s1, g_sk.eFork, 0);

    // s1 (high prio): weight prep
    k_wprep<<<9*384, 256, 0, g_sk.s1>>>(smooth_w);
    cudaEventRecord(g_sk.eW, g_sk.s1);

    // origin: input LN
    k_ln_in<<<NPIX/8, 256>>>(x, ln_in_g, ln_in_b);
    cudaEventRecord(g_sk.eL, 0);

    // s1: attention chain
    cudaStreamWaitEvent(g_sk.s1, g_sk.eL, 0);
    k_dwn<<<dim3(NDIL/2, NPIX/1024), 256, 0, g_sk.s1>>>(dwn_w, dwn_b);
    k_kqv<<<dim3(HH, NB, NDIL), 64, 0, g_sk.s1>>>(k_w, k_b, q_w, q_b, v_w, v_b);
    k_softstats<<<NDIL*NB*DF, 256, 0, g_sk.s1>>>();
    k_attn_ln<<<dim3(HW/256, NDIL*NB), 256, 0, g_sk.s1>>>(ln_up_g, ln_up_b);
    cudaEventRecord(g_sk.eChain, g_sk.s1);

    // origin: xn-part of smooth conv
    cudaStreamWaitEvent(0, g_sk.eW, 0);
    k_smooth_p1<<<dim3(NB*HH, 2), 256, K6_SMEM>>>();

    // join: attn-part + fused output LN -> out
    cudaStreamWaitEvent(0, g_sk.eChain, 0);
    k_smooth_p2f<<<NB*HH*2, 256, P2F_SMEM>>>(smooth_b, ln_out_g, ln_out_b, out);
}

// round 14
// speedup vs baseline: 1.0568x; 1.0568x over previous
#include <cuda_runtime.h>
#include <cuda_fp16.h>
#include <cstdint>

#define NB 4
#define HH 128
#define WWD 128
#define CC 256
#define NDIL 16
#define DF 8
#define CATC 384
#define HW (HH*WWD)
#define NPIX (NB*HW)
#define EPSF 1e-3f

// ---------------- scratch (static device globals: allocation-free) ----------------
__device__ float g_x32[(size_t)NPIX*CC];
__device__ __half g_hf[(size_t)NPIX*CATC];
__device__ float g_dx [(size_t)NDIL*NPIX*DF];
__device__ float g_kq [(size_t)NDIL*NB*DF*HW];
__device__ float g_v  [(size_t)NDIL*NPIX*DF];
__device__ float g_pre[(size_t)NPIX*CC];
__device__ float g_smax[NDIL*NB*DF];
__device__ float g_sinv[NDIL*NB*DF];
__device__ __half g_Wh[(size_t)9*256*384];

// ---------------- stream kit ----------------
namespace {
struct StreamKit {
    cudaStream_t s1;
    cudaEvent_t eFork, eW, eL, eChain;
    StreamKit(){
        int lo = 0, hi = 0;
        cudaDeviceGetStreamPriorityRange(&lo, &hi);
        cudaStreamCreateWithPriority(&s1, cudaStreamNonBlocking, hi);
        cudaEventCreateWithFlags(&eFork,  cudaEventDisableTiming);
        cudaEventCreateWithFlags(&eW,     cudaEventDisableTiming);
        cudaEventCreateWithFlags(&eL,     cudaEventDisableTiming);
        cudaEventCreateWithFlags(&eChain, cudaEventDisableTiming);
    }
};
StreamKit g_sk;
}

// ---------------- f32x2 helpers ----------------
__device__ __forceinline__ unsigned long long dup2(float f){
    unsigned long long r; unsigned u = __float_as_uint(f);
    asm("mov.b64 %0, {%1, %1};" : "=l"(r) : "r"(u));
    return r;
}
__device__ __forceinline__ unsigned long long ffma2(unsigned long long a, unsigned long long b, unsigned long long c){
    unsigned long long d;
    asm("fma.rn.f32x2 %0, %1, %2, %3;" : "=l"(d) : "l"(a), "l"(b), "l"(c));
    return d;
}
__device__ __forceinline__ float2 unpk(unsigned long long v){
    unsigned lo, hi;
    asm("mov.b64 {%0, %1}, %2;" : "=r"(lo), "=r"(hi) : "l"(v));
    return make_float2(__uint_as_float(lo), __uint_as_float(hi));
}

// ---------------- warp MMA + cp.async plumbing ----------------
__device__ __forceinline__ uint32_t smem_u32(const void* p){
    uint32_t a;
    asm("{ .reg .u64 t; cvta.to.shared.u64 t, %1; cvt.u32.u64 %0, t; }" : "=r"(a) : "l"(p));
    return a;
}
__device__ __forceinline__ void ldsm4(uint32_t* r, uint32_t addr){
    asm volatile("ldmatrix.sync.aligned.m8n8.x4.shared.b16 {%0,%1,%2,%3}, [%4];"
        : "=r"(r[0]), "=r"(r[1]), "=r"(r[2]), "=r"(r[3]) : "r"(addr));
}
__device__ __forceinline__ void mma16816h(float* c, const uint32_t* a, const uint32_t* b){
    asm volatile("mma.sync.aligned.m16n8k16.row.col.f32.f16.f16.f32 "
        "{%0,%1,%2,%3}, {%4,%5,%6,%7}, {%8,%9}, {%0,%1,%2,%3};"
        : "+f"(c[0]), "+f"(c[1]), "+f"(c[2]), "+f"(c[3])
        : "r"(a[0]), "r"(a[1]), "r"(a[2]), "r"(a[3]), "r"(b[0]), "r"(b[1]));
}
__device__ __forceinline__ void cpa16(uint32_t dst, const void* src, uint32_t srcsize){
    asm volatile("cp.async.cg.shared.global [%0], [%1], 16, %2;"
        :: "r"(dst), "l"(src), "r"(srcsize) : "memory");
}
#define CP_COMMIT() asm volatile("cp.async.commit_group;" ::: "memory")
#define CP_WAIT1()  asm volatile("cp.async.wait_group 1;" ::: "memory")
#define CP_WAIT0()  asm volatile("cp.async.wait_group 0;" ::: "memory")

__device__ __forceinline__ void store_h8(__half* hp, const float* v){
    __half hh[8];
    #pragma unroll
    for (int j=0;j<8;j++) hh[j] = __float2half_rn(v[j]);
    *(uint4*)hp = *(uint4*)hh;
}

// ---------------- K0: weight prep ----------------
__global__ __launch_bounds__(256) void k_wprep(const float* __restrict__ W){
    int idx = blockIdx.x*256 + threadIdx.x;
    int oc = idx & 255;
    int rest = idx >> 8;
    int ch = rest % 384, tap = rest / 384;
    float w = W[idx];
    size_t o = ((size_t)(tap*256 + oc))*384 + ch;
    g_Wh[o] = __float2half_rn(w);
}

// ---------------- K1: input LayerNorm ----------------
__global__ __launch_bounds__(256) void k_ln_in(const float* __restrict__ x,
                                               const float* __restrict__ gg, const float* __restrict__ bb){
    int gw = (blockIdx.x*blockDim.x + threadIdx.x) >> 5;
    int lane = threadIdx.x & 31;
    if (gw >= NPIX) return;
    const float4* sp = (const float4*)(x + (size_t)gw*CC);
    float4 a0 = sp[lane*2], a1 = sp[lane*2+1];
    float s = a0.x+a0.y+a0.z+a0.w + a1.x+a1.y+a1.z+a1.w;
    #pragma unroll
    for (int o=16;o;o>>=1) s += __shfl_xor_sync(0xffffffffu, s, o);
    float m = s * (1.0f/256.0f);
    float d[8] = {a0.x-m,a0.y-m,a0.z-m,a0.w-m,a1.x-m,a1.y-m,a1.z-m,a1.w-m};
    float q = 0.f;
    #pragma unroll
    for (int j=0;j<8;j++) q += d[j]*d[j];
    #pragma unroll
    for (int o=16;o;o>>=1) q += __shfl_xor_sync(0xffffffffu, q, o);
    float r = rsqrtf(q*(1.0f/256.0f) + EPSF);
    const float4* gp = (const float4*)gg; const float4* bp = (const float4*)bb;
    float4 g0 = gp[lane*2], g1 = gp[lane*2+1];
    float4 b0 = bp[lane*2], b1 = bp[lane*2+1];
    float gv[8] = {g0.x,g0.y,g0.z,g0.w,g1.x,g1.y,g1.z,g1.w};
    float bv[8] = {b0.x,b0.y,b0.z,b0.w,b1.x,b1.y,b1.z,b1.w};
    float o[8];
    #pragma unroll
    for (int j=0;j<8;j++) o[j] = d[j]*r*gv[j] + bv[j];
    float* dp = g_x32 + (size_t)gw*CC + lane*8;
    *(float4*)dp = make_float4(o[0],o[1],o[2],o[3]);
    *(float4*)(dp+4) = make_float4(o[4],o[5],o[6],o[7]);
    store_h8(g_hf + (size_t)gw*CATC + lane*8, o);
}

// ---------------- output LayerNorm over 256 channels ----------------
__global__ __launch_bounds__(256) void k_ln_out(const float* __restrict__ gg, const float* __restrict__ bb,
                                                float* __restrict__ out){
    int gw = (blockIdx.x*blockDim.x + threadIdx.x) >> 5;
    int lane = threadIdx.x & 31;
    if (gw >= NPIX) return;
    const float4* sp = (const float4*)(g_pre + (size_t)gw*CC);
    float4 a0 = sp[lane*2], a1 = sp[lane*2+1];
    float s = a0.x+a0.y+a0.z+a0.w + a1.x+a1.y+a1.z+a1.w;
    #pragma unroll
    for (int o=16;o;o>>=1) s += __shfl_xor_sync(0xffffffffu, s, o);
    float m = s * (1.0f/256.0f);
    float d0=a0.x-m, d1=a0.y-m, d2=a0.z-m, d3=a0.w-m;
    float d4=a1.x-m, d5=a1.y-m, d6=a1.z-m, d7=a1.w-m;
    float q = d0*d0+d1*d1+d2*d2+d3*d3+d4*d4+d5*d5+d6*d6+d7*d7;
    #pragma unroll
    for (int o=16;o;o>>=1) q += __shfl_xor_sync(0xffffffffu, q, o);
    float r = rsqrtf(q*(1.0f/256.0f) + EPSF);
    const float4* gp = (const float4*)gg; const float4* bp = (const float4*)bb;
    float4 g0 = gp[lane*2], g1 = gp[lane*2+1];
    float4 b0 = bp[lane*2], b1 = bp[lane*2+1];
    float4 o0 = make_float4(d0*r*g0.x+b0.x, d1*r*g0.y+b0.y, d2*r*g0.z+b0.z, d3*r*g0.w+b0.w);
    float4 o1 = make_float4(d4*r*g1.x+b1.x, d5*r*g1.y+b1.y, d6*r*g1.z+b1.z, d7*r*g1.w+b1.w);
    float* dp = out + (size_t)gw*CC + lane*8;
    *(float4*)dp = o0;
    *(float4*)(dp+4) = o1;
}

// ---------------- K2: 1x1 down conv (256 -> 8), 2 branches per CTA, relu, f32x2 ----------------
__global__ __launch_bounds__(256) void k_dwn(const float* __restrict__ Wd, const float* __restrict__ Bd){
    __shared__ __align__(16) float ws[2*CC*DF];
    __shared__ float xs[8][1024];
    const int i0 = blockIdx.x * 2;
    const int px0 = blockIdx.y * 1024;
    const int t = threadIdx.x;

    const float4* wsrc = (const float4*)(Wd + (size_t)i0*CC*DF);
    for (int idx = t; idx < 2*CC*DF/4; idx += 256) ((float4*)ws)[idx] = wsrc[idx];

    unsigned long long acc[2][4][4];
    #pragma unroll
    for (int br=0;br<2;br++)
        #pragma unroll
        for (int j=0;j<4;j++)
            #pragma unroll
            for (int k=0;k<4;k++) acc[br][j][k] = 0ull;

    for (int cc = 0; cc < CC; cc += 8){
        __syncthreads();
        #pragma unroll
        for (int j = 0; j < 4; j++){
            int p = t + 256*j;
            const float* src = g_x32 + (size_t)(px0 + p)*CC + cc;
            float4 v0 = *(const float4*)src;
            float4 v1 = *(const float4*)(src+4);
            xs[0][p]=v0.x; xs[1][p]=v0.y; xs[2][p]=v0.z; xs[3][p]=v0.w;
            xs[4][p]=v1.x; xs[5][p]=v1.y; xs[6][p]=v1.z; xs[7][p]=v1.w;
        }
        __syncthreads();
        #pragma unroll
        for (int c = 0; c < 8; c++){
            unsigned long long xd0 = dup2(xs[c][t]),     xd1 = dup2(xs[c][t+256]);
            unsigned long long xd2 = dup2(xs[c][t+512]), xd3 = dup2(xs[c][t+768]);
            #pragma unroll
            for (int br = 0; br < 2; br++){
                const unsigned long long* wp = (const unsigned long long*)&ws[br*CC*DF + (cc+c)*8];
                unsigned long long w0=wp[0], w1=wp[1], w2=wp[2], w3=wp[3];
                acc[br][0][0]=ffma2(xd0,w0,acc[br][0][0]); acc[br][0][1]=ffma2(xd0,w1,acc[br][0][1]);
                acc[br][0][2]=ffma2(xd0,w2,acc[br][0][2]); acc[br][0][3]=ffma2(xd0,w3,acc[br][0][3]);
                acc[br][1][0]=ffma2(xd1,w0,acc[br][1][0]); acc[br][1][1]=ffma2(xd1,w1,acc[br][1][1]);
                acc[br][1][2]=ffma2(xd1,w2,acc[br][1][2]); acc[br][1][3]=ffma2(xd1,w3,acc[br][1][3]);
                acc[br][2][0]=ffma2(xd2,w0,acc[br][2][0]); acc[br][2][1]=ffma2(xd2,w1,acc[br][2][1]);
                acc[br][2][2]=ffma2(xd2,w2,acc[br][2][2]); acc[br][2][3]=ffma2(xd2,w3,acc[br][2][3]);
                acc[br][3][0]=ffma2(xd3,w0,acc[br][3][0]); acc[br][3][1]=ffma2(xd3,w1,acc[br][3][1]);
                acc[br][3][2]=ffma2(xd3,w2,acc[br][3][2]); acc[br][3][3]=ffma2(xd3,w3,acc[br][3][3]);
            }
        }
    }
    #pragma unroll
    for (int br = 0; br < 2; br++){
        float bb[8];
        #pragma unroll
        for (int oc=0;oc<8;oc++) bb[oc] = Bd[(i0+br)*8+oc];
        #pragma unroll
        for (int j=0;j<4;j++){
            int p = px0 + t + 256*j;
            float o[8];
            #pragma unroll
            for (int k=0;k<4;k++){
                float2 f = unpk(acc[br][j][k]);
                o[2*k]   = fmaxf(f.x + bb[2*k],   0.f);
                o[2*k+1] = fmaxf(f.y + bb[2*k+1], 0.f);
            }
            float* dp = g_dx + ((size_t)(i0+br)*NPIX + p)*DF;
            *(float4*)dp     = make_float4(o[0],o[1],o[2],o[3]);
            *(float4*)(dp+4) = make_float4(o[4],o[5],o[6],o[7]);
        }
    }
}

// ---------------- K3: k,q,v 3x3 dilated convs + relu + kq product ----------------
__global__ __launch_bounds__(64) void k_kqv(const float* __restrict__ Kw, const float* __restrict__ Kb,
                                            const float* __restrict__ Qw, const float* __restrict__ Qb,
                                            const float* __restrict__ Vw, const float* __restrict__ Vb){
    __shared__ float xs[3][8][128];
    __shared__ float wsk[576], wsq[576], wsv[576];
    __shared__ float sbk[8], sbq[8], sbv[8];

    const int h = blockIdx.x, n = blockIdx.y, i = blockIdx.z;
    const int d = i + 1;
    const int t = threadIdx.x;

    const float* dxb = g_dx + ((size_t)i*NPIX + (size_t)n*HW)*DF;
    #pragma unroll
    for (int r = 0; r < 3; r++){
        int hh = h + (r-1)*d;
        if ((unsigned)hh < (unsigned)HH){
            #pragma unroll
            for (int j = 0; j < 2; j++){
                int w = t + 64*j;
                const float* src = dxb + (size_t)(hh*WWD + w)*DF;
                float4 v0 = *(const float4*)src;
                float4 v1 = *(const float4*)(src+4);
                xs[r][0][w]=v0.x; xs[r][1][w]=v0.y; xs[r][2][w]=v0.z; xs[r][3][w]=v0.w;
                xs[r][4][w]=v1.x; xs[r][5][w]=v1.y; xs[r][6][w]=v1.z; xs[r][7][w]=v1.w;
            }
        } else {
            for (int idx = t; idx < 8*128; idx += 64) (&xs[r][0][0])[idx] = 0.f;
        }
    }
    for (int idx = t; idx < 576; idx += 64){
        wsk[idx] = Kw[(size_t)i*576 + idx];
        wsq[idx] = Qw[(size_t)i*576 + idx];
        wsv[idx] = Vw[(size_t)i*576 + idx];
    }
    if (t < 8){ sbk[t]=Kb[i*8+t]; sbq[t]=Qb[i*8+t]; sbv[t]=Vb[i*8+t]; }
    __syncthreads();

    const int w0 = t, w1 = t + 64;
    float ak0[8], ak1[8], aq0[8], aq1[8], av0[8], av1[8];
    #pragma unroll
    for (int c=0;c<8;c++){ ak0[c]=ak1[c]=aq0[c]=aq1[c]=av0[c]=av1[c]=0.f; }

    #pragma unroll 1
    for (int tap = 0; tap < 9; tap++){
        int ky = tap/3, kx = tap%3;
        int c0 = w0 + (kx-1)*d; bool ok0 = (unsigned)c0 < (unsigned)WWD;
        int c1 = w1 + (kx-1)*d; bool ok1 = (unsigned)c1 < (unsigned)WWD;
        const float* xr = &xs[ky][0][0];
        #pragma unroll
        for (int ci = 0; ci < 8; ci++){
            float x0 = ok0 ? xr[ci*128 + c0] : 0.f;
            float x1 = ok1 ? xr[ci*128 + c1] : 0.f;
            const float* wk = &wsk[(tap*8+ci)*8];
            const float* wq = &wsq[(tap*8+ci)*8];
            const float* wv = &wsv[(tap*8+ci)*8];
            #pragma unroll
            for (int co = 0; co < 8; co++){
                ak0[co] += x0*wk[co]; ak1[co] += x1*wk[co];
                aq0[co] += x0*wq[co]; aq1[co] += x1*wq[co];
                av0[co] += x0*wv[co]; av1[co] += x1*wv[co];
            }
        }
    }

    float kq0[8], kq1[8], vv0[8], vv1[8];
    #pragma unroll
    for (int co = 0; co < 8; co++){
        float k0 = fmaxf(ak0[co]+sbk[co],0.f), k1 = fmaxf(ak1[co]+sbk[co],0.f);
        float q0 = fmaxf(aq0[co]+sbq[co],0.f), q1 = fmaxf(aq1[co]+sbq[co],0.f);
        vv0[co]  = fmaxf(av0[co]+sbv[co],0.f); vv1[co] = fmaxf(av1[co]+sbv[co],0.f);
        kq0[co] = k0*q0; kq1[co] = k1*q1;
    }
    const int in = i*NB + n;
    const int hwb = h*WWD;
    #pragma unroll
    for (int co = 0; co < 8; co++){
        float* kp = g_kq + ((size_t)in*DF + co)*HW + hwb;
        kp[w0] = kq0[co]; kp[w1] = kq1[co];
    }
    float* vp0 = g_v + ((size_t)i*NPIX + (size_t)n*HW + hwb + w0)*DF;
    float* vp1 = g_v + ((size_t)i*NPIX + (size_t)n*HW + hwb + w1)*DF;
    *(float4*)vp0     = make_float4(vv0[0],vv0[1],vv0[2],vv0[3]);
    *(float4*)(vp0+4) = make_float4(vv0[4],vv0[5],vv0[6],vv0[7]);
    *(float4*)vp1     = make_float4(vv1[0],vv1[1],vv1[2],vv1[3]);
    *(float4*)(vp1+4) = make_float4(vv1[4],vv1[5],vv1[6],vv1[7]);
}

// ---------------- K4: softmax stats ----------------
__global__ __launch_bounds__(256) void k_softstats(){
    const int plane = blockIdx.x;
    const float4* p = (const float4*)(g_kq + (size_t)plane*HW);
    const int t = threadIdx.x, lane = t & 31, warp = t >> 5;
    __shared__ float red[8];

    float m = -1e30f;
    for (int idx = t; idx < HW/4; idx += 256){
        float4 v = p[idx];
        m = fmaxf(m, fmaxf(fmaxf(v.x,v.y), fmaxf(v.z,v.w)));
    }
    #pragma unroll
    for (int o=16;o;o>>=1) m = fmaxf(m, __shfl_xor_sync(0xffffffffu, m, o));
    if (lane==0) red[warp] = m;
    __syncthreads();
    float bm = red[0];
    #pragma unroll
    for (int k=1;k<8;k++) bm = fmaxf(bm, red[k]);
    __syncthreads();

    float s = 0.f;
    for (int idx = t; idx < HW/4; idx += 256){
        float4 v = p[idx];
        s += __expf(v.x-bm) + __expf(v.y-bm) + __expf(v.z-bm) + __expf(v.w-bm);
    }
    #pragma unroll
    for (int o=16;o;o>>=1) s += __shfl_xor_sync(0xffffffffu, s, o);
    if (lane==0) red[warp] = s;
    __syncthreads();
    if (t == 0){
        float tot = 0.f;
        #pragma unroll
        for (int k=0;k<8;k++) tot += red[k];
        g_smax[plane] = bm;
        g_sinv[plane] = 1.0f / tot;
    }
}

// ---------------- K5: softmax*v + LN over DF -> fp16 cat channels ----------------
__global__ __launch_bounds__(256) void k_attn_ln(const float* __restrict__ gup, const float* __restrict__ bup){
    __shared__ float sm[8], si[8], sg[8], sb[8];
    const int in = blockIdx.y;
    const int t = threadIdx.x;
    if (t < 8){ sm[t]=g_smax[in*DF+t]; si[t]=g_sinv[in*DF+t]; sg[t]=gup[t]; sb[t]=bup[t]; }
    __syncthreads();
    const int hw = blockIdx.x*256 + t;
    const int i = in >> 2, n = in & 3;

    size_t vb = ((size_t)i*NPIX + (size_t)n*HW + hw)*DF;
    float4 v0 = *(const float4*)&g_v[vb];
    float4 v1 = *(const float4*)&g_v[vb+4];
    float vv[8] = {v0.x,v0.y,v0.z,v0.w,v1.x,v1.y,v1.z,v1.w};

    float y[8]; float s = 0.f;
    #pragma unroll
    for (int c = 0; c < 8; c++){
        float kq = g_kq[((size_t)in*DF + c)*HW + hw];
        float a = __expf(kq - sm[c]) * si[c];
        y[c] = a * vv[c];
        s += y[c];
    }
    float mean = s * 0.125f, q = 0.f;
    #pragma unroll
    for (int c = 0; c < 8; c++){ float dd = y[c]-mean; q += dd*dd; }
    float r = rsqrtf(q*0.125f + EPSF);
    float o[8];
    #pragma unroll
    for (int c = 0; c < 8; c++) o[c] = (y[c]-mean)*r*sg[c] + sb[c];

    size_t ob = ((size_t)(n*HW + hw))*CATC + CC + i*DF;
    store_h8(g_hf + ob, o);
}

// ---------------- K6: smooth 3x3 conv 384->256, HMMA fp16, split xn/attn ----------------
// 3-buffer ring, 2-deep cp.async prefetch, single barrier per stage.
#define BUF_BYTES 32768
#define K6_SMEM (1024 + 3*BUF_BYTES)

template<int NSTAGE, int CCDIV, int CCBASE, bool INITG, bool FINAL>
__global__ void __launch_bounds__(256, 2) k_smooth_part(const float* __restrict__ bias){
    extern __shared__ __align__(128) char smem[];
    float* s_bias = (float*)smem;
    const uint32_t sb0 = smem_u32(smem) + 1024;

    const int t = threadIdx.x;
    const int lane = t & 31, wid = t >> 5;
    const int wm = wid & 3, wn = wid >> 2;
    const int row_id = blockIdx.x;
    const int n = row_id >> 7, h = row_id & 127;
    const int oc0 = blockIdx.y * 128;

    if (FINAL && t < 128) s_bias[t] = bias[oc0 + t];

    const int srow = t >> 1;
    const int cb   = (t & 1) * 4;

    uint32_t dsw[4];
    #pragma unroll
    for (int j = 0; j < 4; j++){
        uint32_t off = (uint32_t)srow*128 + (uint32_t)(cb + j)*16;
        dsw[j] = off ^ ((off >> 3) & 0x70);
    }

    auto stage_issue = [&](int s, int b){
        const int tap = s / CCDIV, cc = CCBASE + (s % CCDIV) * 64;
        const int dy = tap/3 - 1, dxo = tap%3 - 1;
        const int hh = h + dy;
        const int ww = srow + dxo;
        const bool ok = ((unsigned)hh < (unsigned)HH) && ((unsigned)ww < (unsigned)WWD);
        const int hcl = ok ? hh : 0, wcl = ok ? ww : 0;
        const uint32_t sz = ok ? 16u : 0u;
        const uint32_t base = sb0 + (uint32_t)b*BUF_BYTES;
        const size_t abase = ((size_t)((n*HH + hcl)*WWD + wcl))*CATC + cc + cb*8;
        const size_t wbase = ((size_t)(tap*256 + oc0 + srow))*CATC + cc + cb*8;
        #pragma unroll
        for (int j = 0; j < 4; j++){
            cpa16(base +         dsw[j], g_hf + abase + j*8, sz);
            cpa16(base + 16384 + dsw[j], g_Wh + wbase + j*8, 16u);
        }
        CP_COMMIT();
    };

    const int pix0 = row_id * 128;
    float acc[2][8][4];
    if (INITG){
        #pragma unroll
        for (int mt = 0; mt < 2; mt++){
            #pragma unroll
            for (int nt = 0; nt < 8; nt++){
                int r = wm*32 + mt*16 + (lane >> 2);
                int cidx = wn*64 + nt*8 + (lane & 3)*2;
                float2 v0 = *(const float2*)(g_pre + (size_t)(pix0 + r)*CC + oc0 + cidx);
                float2 v1 = *(const float2*)(g_pre + (size_t)(pix0 + r + 8)*CC + oc0 + cidx);
                acc[mt][nt][0]=v0.x; acc[mt][nt][1]=v0.y; acc[mt][nt][2]=v1.x; acc[mt][nt][3]=v1.y;
            }
        }
    } else {
        #pragma unroll
        for (int a=0;a<2;a++)
            #pragma unroll
            for (int b=0;b<8;b++)
                #pragma unroll
                for (int c=0;c<4;c++) acc[a][b][c] = 0.f;
    }

    // 2-deep prefetch prologue
    stage_issue(0, 0);
    if (NSTAGE > 1) stage_issue(1, 1);

    #pragma unroll 1
    for (int s = 0; s < NSTAGE; s++){
        if (s + 1 < NSTAGE){
            CP_WAIT1();          // stage s's group complete (stage s+1 may be in flight)
        } else {
            CP_WAIT0();
        }
        __syncthreads();         // all warps done computing stage s-1 -> buffer (s+2)%3 free
        if (s + 2 < NSTAGE){
            int b2 = (s + 2) % 3;
            stage_issue(s + 2, b2);
        }

        int bcur = s % 3;
        const uint32_t base = sb0 + (uint32_t)bcur*BUF_BYTES;
        const uint32_t aB = base, bB = base + 16384;

        #pragma unroll
        for (int ks = 0; ks < 4; ks++){
            uint32_t ah[2][4];
            #pragma unroll
            for (int mt = 0; mt < 2; mt++){
                uint32_t arow = (uint32_t)(wm*32 + mt*16 + (lane & 15));
                uint32_t ac16 = (uint32_t)(ks*2 + (lane >> 4));
                uint32_t off = arow*128 + ac16*16;
                uint32_t sw = off ^ ((off >> 3) & 0x70);
                ldsm4(ah[mt], aB + sw);
            }
            uint32_t brow = (uint32_t)(wn*64 + ((lane >> 4) << 3) + (lane & 7));
            uint32_t bc16 = (uint32_t)(ks*2 + ((lane >> 3) & 1));
            #pragma unroll
            for (int g = 0; g < 4; g++){
                uint32_t off = (brow + (uint32_t)g*16)*128 + bc16*16;
                uint32_t sw = off ^ ((off >> 3) & 0x70);
                uint32_t bfr[4];
                ldsm4(bfr, bB + sw);
                mma16816h(acc[0][2*g],   ah[0], bfr);
                mma16816h(acc[1][2*g],   ah[1], bfr);
                mma16816h(acc[0][2*g+1], ah[0], bfr+2);
                mma16816h(acc[1][2*g+1], ah[1], bfr+2);
            }
        }
    }

    // Epilogue
    #pragma unroll
    for (int mt = 0; mt < 2; mt++){
        #pragma unroll
        for (int nt = 0; nt < 8; nt++){
            int r = wm*32 + mt*16 + (lane >> 2);
            int cidx = wn*64 + nt*8 + (lane & 3)*2;
            float* p0 = g_pre + (size_t)(pix0 + r)*CC + oc0 + cidx;
            float* p1 = g_pre + (size_t)(pix0 + r + 8)*CC + oc0 + cidx;
            if (FINAL){
                float b0 = s_bias[cidx], b1 = s_bias[cidx+1];
                *(float2*)p0 = make_float2(fmaxf(acc[mt][nt][0]+b0, 0.f), fmaxf(acc[mt][nt][1]+b1, 0.f));
                *(float2*)p1 = make_float2(fmaxf(acc[mt][nt][2]+b0, 0.f), fmaxf(acc[mt][nt][3]+b1, 0.f));
            } else {
                *(float2*)p0 = make_float2(acc[mt][nt][0], acc[mt][nt][1]);
                *(float2*)p1 = make_float2(acc[mt][nt][2], acc[mt][nt][3]);
            }
        }
    }
}

// ---------------- launch ----------------
extern "C" void kernel_launch(void* const* d_in, const int* in_sizes, int n_in,
                              void* d_out, int out_size){
    (void)in_sizes; (void)n_in; (void)out_size;
    const float* x        = (const float*)d_in[0];
    const float* dwn_w    = (const float*)d_in[1];
    const float* dwn_b    = (const float*)d_in[2];
    const float* k_w      = (const float*)d_in[3];
    const float* k_b      = (const float*)d_in[4];
    const float* q_w      = (const float*)d_in[5];
    const float* q_b      = (const float*)d_in[6];
    const float* v_w      = (const float*)d_in[7];
    const float* v_b      = (const float*)d_in[8];
    const float* smooth_w = (const float*)d_in[9];
    const float* smooth_b = (const float*)d_in[10];
    const float* ln_in_g  = (const float*)d_in[11];
    const float* ln_in_b  = (const float*)d_in[12];
    const float* ln_up_g  = (const float*)d_in[13];
    const float* ln_up_b  = (const float*)d_in[14];
    const float* ln_out_g = (const float*)d_in[15];
    const float* ln_out_b = (const float*)d_in[16];
    float* out = (float*)d_out;

    cudaFuncSetAttribute(k_smooth_part<36,4,0,false,false>,
                         cudaFuncAttributeMaxDynamicSharedMemorySize, K6_SMEM);
    cudaFuncSetAttribute(k_smooth_part<18,2,256,true,true>,
                         cudaFuncAttributeMaxDynamicSharedMemorySize, K6_SMEM);

    // fork: s1 joins capture via event recorded on origin stream first
    cudaEventRecord(g_sk.eFork, 0);
    cudaStreamWaitEvent(g_sk.s1, g_sk.eFork, 0);

    // s1 (high prio): weight prep
    k_wprep<<<9*384, 256, 0, g_sk.s1>>>(smooth_w);
    cudaEventRecord(g_sk.eW, g_sk.s1);

    // origin: input LN
    k_ln_in<<<NPIX/8, 256>>>(x, ln_in_g, ln_in_b);
    cudaEventRecord(g_sk.eL, 0);

    // s1: attention chain
    cudaStreamWaitEvent(g_sk.s1, g_sk.eL, 0);
    k_dwn<<<dim3(NDIL/2, NPIX/1024), 256, 0, g_sk.s1>>>(dwn_w, dwn_b);
    k_kqv<<<dim3(HH, NB, NDIL), 64, 0, g_sk.s1>>>(k_w, k_b, q_w, q_b, v_w, v_b);
    k_softstats<<<NDIL*NB*DF, 256, 0, g_sk.s1>>>();
    k_attn_ln<<<dim3(HW/256, NDIL*NB), 256, 0, g_sk.s1>>>(ln_up_g, ln_up_b);
    cudaEventRecord(g_sk.eChain, g_sk.s1);

    // origin: xn-part of smooth conv
    cudaStreamWaitEvent(0, g_sk.eW, 0);
    k_smooth_part<36,4,0,false,false><<<dim3(NB*HH, 2), 256, K6_SMEM>>>(smooth_b);

    // join: attn-part
    cudaStreamWaitEvent(0, g_sk.eChain, 0);
    k_smooth_part<18,2,256,true,true><<<dim3(NB*HH, 2), 256, K6_SMEM>>>(smooth_b);
    k_ln_out<<<NPIX/8, 256>>>(ln_out_g, ln_out_b, out);
}

// round 15
// speedup vs baseline: 1.1256x; 1.0651x over previous
#include <cuda_runtime.h>
#include <cuda_fp16.h>
#include <cstdint>

#define NB 4
#define HH 128
#define WWD 128
#define CC 256
#define NDIL 16
#define DF 8
#define CATC 384
#define HW (HH*WWD)
#define NPIX (NB*HW)
#define EPSF 1e-3f

// ---------------- scratch (static device globals: allocation-free) ----------------
__device__ float g_x32[(size_t)NPIX*CC];
__device__ __half g_hf[(size_t)NPIX*CATC];
__device__ float g_dx [(size_t)NDIL*NPIX*DF];
__device__ float g_kq [(size_t)NDIL*NB*DF*HW];
__device__ float g_v  [(size_t)NDIL*NPIX*DF];
__device__ float g_pre[(size_t)NPIX*CC];
__device__ float g_smax[NDIL*NB*DF];
__device__ float g_sinv[NDIL*NB*DF];
__device__ __half g_Wh[(size_t)9*256*384];

// ---------------- stream kit ----------------
namespace {
struct StreamKit {
    cudaStream_t s1;
    cudaEvent_t eFork, eL, eP1;
    StreamKit(){
        int lo = 0, hi = 0;
        cudaDeviceGetStreamPriorityRange(&lo, &hi);   // hi = highest priority
        cudaStreamCreateWithPriority(&s1, cudaStreamNonBlocking, hi);
        cudaEventCreateWithFlags(&eFork, cudaEventDisableTiming);
        cudaEventCreateWithFlags(&eL,    cudaEventDisableTiming);
        cudaEventCreateWithFlags(&eP1,   cudaEventDisableTiming);
    }
};
StreamKit g_sk;
}

// ---------------- f32x2 helpers ----------------
__device__ __forceinline__ unsigned long long dup2(float f){
    unsigned long long r; unsigned u = __float_as_uint(f);
    asm("mov.b64 %0, {%1, %1};" : "=l"(r) : "r"(u));
    return r;
}
__device__ __forceinline__ unsigned long long ffma2(unsigned long long a, unsigned long long b, unsigned long long c){
    unsigned long long d;
    asm("fma.rn.f32x2 %0, %1, %2, %3;" : "=l"(d) : "l"(a), "l"(b), "l"(c));
    return d;
}
__device__ __forceinline__ float2 unpk(unsigned long long v){
    unsigned lo, hi;
    asm("mov.b64 {%0, %1}, %2;" : "=r"(lo), "=r"(hi) : "l"(v));
    return make_float2(__uint_as_float(lo), __uint_as_float(hi));
}

// ---------------- warp MMA + cp.async plumbing ----------------
__device__ __forceinline__ uint32_t smem_u32(const void* p){
    uint32_t a;
    asm("{ .reg .u64 t; cvta.to.shared.u64 t, %1; cvt.u32.u64 %0, t; }" : "=r"(a) : "l"(p));
    return a;
}
__device__ __forceinline__ void ldsm4(uint32_t* r, uint32_t addr){
    asm volatile("ldmatrix.sync.aligned.m8n8.x4.shared.b16 {%0,%1,%2,%3}, [%4];"
        : "=r"(r[0]), "=r"(r[1]), "=r"(r[2]), "=r"(r[3]) : "r"(addr));
}
__device__ __forceinline__ void mma16816h(float* c, const uint32_t* a, const uint32_t* b){
    asm volatile("mma.sync.aligned.m16n8k16.row.col.f32.f16.f16.f32 "
        "{%0,%1,%2,%3}, {%4,%5,%6,%7}, {%8,%9}, {%0,%1,%2,%3};"
        : "+f"(c[0]), "+f"(c[1]), "+f"(c[2]), "+f"(c[3])
        : "r"(a[0]), "r"(a[1]), "r"(a[2]), "r"(a[3]), "r"(b[0]), "r"(b[1]));
}
__device__ __forceinline__ void cpa16(uint32_t dst, const void* src, uint32_t srcsize){
    asm volatile("cp.async.cg.shared.global [%0], [%1], 16, %2;"
        :: "r"(dst), "l"(src), "r"(srcsize) : "memory");
}
#define CP_COMMIT() asm volatile("cp.async.commit_group;" ::: "memory")
#define CP_WAIT1()  asm volatile("cp.async.wait_group 1;" ::: "memory")
#define CP_WAIT0()  asm volatile("cp.async.wait_group 0;" ::: "memory")

__device__ __forceinline__ void store_h8(__half* hp, const float* v){
    __half hh[8];
    #pragma unroll
    for (int j=0;j<8;j++) hh[j] = __float2half_rn(v[j]);
    *(uint4*)hp = *(uint4*)hh;
}

// ---------------- K0: weight prep ----------------
__global__ __launch_bounds__(256) void k_wprep(const float* __restrict__ W){
    int idx = blockIdx.x*256 + threadIdx.x;
    int oc = idx & 255;
    int rest = idx >> 8;
    int ch = rest % 384, tap = rest / 384;
    float w = W[idx];
    size_t o = ((size_t)(tap*256 + oc))*384 + ch;
    g_Wh[o] = __float2half_rn(w);
}

// ---------------- K1: input LayerNorm ----------------
__global__ __launch_bounds__(256) void k_ln_in(const float* __restrict__ x,
                                               const float* __restrict__ gg, const float* __restrict__ bb){
    int gw = (blockIdx.x*blockDim.x + threadIdx.x) >> 5;
    int lane = threadIdx.x & 31;
    if (gw >= NPIX) return;
    const float4* sp = (const float4*)(x + (size_t)gw*CC);
    float4 a0 = sp[lane*2], a1 = sp[lane*2+1];
    float s = a0.x+a0.y+a0.z+a0.w + a1.x+a1.y+a1.z+a1.w;
    #pragma unroll
    for (int o=16;o;o>>=1) s += __shfl_xor_sync(0xffffffffu, s, o);
    float m = s * (1.0f/256.0f);
    float d[8] = {a0.x-m,a0.y-m,a0.z-m,a0.w-m,a1.x-m,a1.y-m,a1.z-m,a1.w-m};
    float q = 0.f;
    #pragma unroll
    for (int j=0;j<8;j++) q += d[j]*d[j];
    #pragma unroll
    for (int o=16;o;o>>=1) q += __shfl_xor_sync(0xffffffffu, q, o);
    float r = rsqrtf(q*(1.0f/256.0f) + EPSF);
    const float4* gp = (const float4*)gg; const float4* bp = (const float4*)bb;
    float4 g0 = gp[lane*2], g1 = gp[lane*2+1];
    float4 b0 = bp[lane*2], b1 = bp[lane*2+1];
    float gv[8] = {g0.x,g0.y,g0.z,g0.w,g1.x,g1.y,g1.z,g1.w};
    float bv[8] = {b0.x,b0.y,b0.z,b0.w,b1.x,b1.y,b1.z,b1.w};
    float o[8];
    #pragma unroll
    for (int j=0;j<8;j++) o[j] = d[j]*r*gv[j] + bv[j];
    float* dp = g_x32 + (size_t)gw*CC + lane*8;
    *(float4*)dp = make_float4(o[0],o[1],o[2],o[3]);
    *(float4*)(dp+4) = make_float4(o[4],o[5],o[6],o[7]);
    store_h8(g_hf + (size_t)gw*CATC + lane*8, o);
}

// ---------------- output LayerNorm over 256 channels ----------------
__global__ __launch_bounds__(256) void k_ln_out(const float* __restrict__ gg, const float* __restrict__ bb,
                                                float* __restrict__ out){
    int gw = (blockIdx.x*blockDim.x + threadIdx.x) >> 5;
    int lane = threadIdx.x & 31;
    if (gw >= NPIX) return;
    const float4* sp = (const float4*)(g_pre + (size_t)gw*CC);
    float4 a0 = sp[lane*2], a1 = sp[lane*2+1];
    float s = a0.x+a0.y+a0.z+a0.w + a1.x+a1.y+a1.z+a1.w;
    #pragma unroll
    for (int o=16;o;o>>=1) s += __shfl_xor_sync(0xffffffffu, s, o);
    float m = s * (1.0f/256.0f);
    float d0=a0.x-m, d1=a0.y-m, d2=a0.z-m, d3=a0.w-m;
    float d4=a1.x-m, d5=a1.y-m, d6=a1.z-m, d7=a1.w-m;
    float q = d0*d0+d1*d1+d2*d2+d3*d3+d4*d4+d5*d5+d6*d6+d7*d7;
    #pragma unroll
    for (int o=16;o;o>>=1) q += __shfl_xor_sync(0xffffffffu, q, o);
    float r = rsqrtf(q*(1.0f/256.0f) + EPSF);
    const float4* gp = (const float4*)gg; const float4* bp = (const float4*)bb;
    float4 g0 = gp[lane*2], g1 = gp[lane*2+1];
    float4 b0 = bp[lane*2], b1 = bp[lane*2+1];
    float4 o0 = make_float4(d0*r*g0.x+b0.x, d1*r*g0.y+b0.y, d2*r*g0.z+b0.z, d3*r*g0.w+b0.w);
    float4 o1 = make_float4(d4*r*g1.x+b1.x, d5*r*g1.y+b1.y, d6*r*g1.z+b1.z, d7*r*g1.w+b1.w);
    float* dp = out + (size_t)gw*CC + lane*8;
    *(float4*)dp = o0;
    *(float4*)(dp+4) = o1;
}

// ---------------- K2: 1x1 down conv (256 -> 8), 2 branches per CTA, relu, f32x2 ----------------
__global__ __launch_bounds__(256) void k_dwn(const float* __restrict__ Wd, const float* __restrict__ Bd){
    __shared__ __align__(16) float ws[2*CC*DF];
    __shared__ float xs[8][1024];
    const int i0 = blockIdx.x * 2;
    const int px0 = blockIdx.y * 1024;
    const int t = threadIdx.x;

    const float4* wsrc = (const float4*)(Wd + (size_t)i0*CC*DF);
    for (int idx = t; idx < 2*CC*DF/4; idx += 256) ((float4*)ws)[idx] = wsrc[idx];

    unsigned long long acc[2][4][4];
    #pragma unroll
    for (int br=0;br<2;br++)
        #pragma unroll
        for (int j=0;j<4;j++)
            #pragma unroll
            for (int k=0;k<4;k++) acc[br][j][k] = 0ull;

    for (int cc = 0; cc < CC; cc += 8){
        __syncthreads();
        #pragma unroll
        for (int j = 0; j < 4; j++){
            int p = t + 256*j;
            const float* src = g_x32 + (size_t)(px0 + p)*CC + cc;
            float4 v0 = *(const float4*)src;
            float4 v1 = *(const float4*)(src+4);
            xs[0][p]=v0.x; xs[1][p]=v0.y; xs[2][p]=v0.z; xs[3][p]=v0.w;
            xs[4][p]=v1.x; xs[5][p]=v1.y; xs[6][p]=v1.z; xs[7][p]=v1.w;
        }
        __syncthreads();
        #pragma unroll
        for (int c = 0; c < 8; c++){
            unsigned long long xd0 = dup2(xs[c][t]),     xd1 = dup2(xs[c][t+256]);
            unsigned long long xd2 = dup2(xs[c][t+512]), xd3 = dup2(xs[c][t+768]);
            #pragma unroll
            for (int br = 0; br < 2; br++){
                const unsigned long long* wp = (const unsigned long long*)&ws[br*CC*DF + (cc+c)*8];
                unsigned long long w0=wp[0], w1=wp[1], w2=wp[2], w3=wp[3];
                acc[br][0][0]=ffma2(xd0,w0,acc[br][0][0]); acc[br][0][1]=ffma2(xd0,w1,acc[br][0][1]);
                acc[br][0][2]=ffma2(xd0,w2,acc[br][0][2]); acc[br][0][3]=ffma2(xd0,w3,acc[br][0][3]);
                acc[br][1][0]=ffma2(xd1,w0,acc[br][1][0]); acc[br][1][1]=ffma2(xd1,w1,acc[br][1][1]);
                acc[br][1][2]=ffma2(xd1,w2,acc[br][1][2]); acc[br][1][3]=ffma2(xd1,w3,acc[br][1][3]);
                acc[br][2][0]=ffma2(xd2,w0,acc[br][2][0]); acc[br][2][1]=ffma2(xd2,w1,acc[br][2][1]);
                acc[br][2][2]=ffma2(xd2,w2,acc[br][2][2]); acc[br][2][3]=ffma2(xd2,w3,acc[br][2][3]);
                acc[br][3][0]=ffma2(xd3,w0,acc[br][3][0]); acc[br][3][1]=ffma2(xd3,w1,acc[br][3][1]);
                acc[br][3][2]=ffma2(xd3,w2,acc[br][3][2]); acc[br][3][3]=ffma2(xd3,w3,acc[br][3][3]);
            }
        }
    }
    #pragma unroll
    for (int br = 0; br < 2; br++){
        float bb[8];
        #pragma unroll
        for (int oc=0;oc<8;oc++) bb[oc] = Bd[(i0+br)*8+oc];
        #pragma unroll
        for (int j=0;j<4;j++){
            int p = px0 + t + 256*j;
            float o[8];
            #pragma unroll
            for (int k=0;k<4;k++){
                float2 f = unpk(acc[br][j][k]);
                o[2*k]   = fmaxf(f.x + bb[2*k],   0.f);
                o[2*k+1] = fmaxf(f.y + bb[2*k+1], 0.f);
            }
            float* dp = g_dx + ((size_t)(i0+br)*NPIX + p)*DF;
            *(float4*)dp     = make_float4(o[0],o[1],o[2],o[3]);
            *(float4*)(dp+4) = make_float4(o[4],o[5],o[6],o[7]);
        }
    }
}

// ---------------- K3: k,q,v 3x3 dilated convs + relu + kq product ----------------
__global__ __launch_bounds__(64) void k_kqv(const float* __restrict__ Kw, const float* __restrict__ Kb,
                                            const float* __restrict__ Qw, const float* __restrict__ Qb,
                                            const float* __restrict__ Vw, const float* __restrict__ Vb){
    __shared__ float xs[3][8][128];
    __shared__ float wsk[576], wsq[576], wsv[576];
    __shared__ float sbk[8], sbq[8], sbv[8];

    const int h = blockIdx.x, n = blockIdx.y, i = blockIdx.z;
    const int d = i + 1;
    const int t = threadIdx.x;

    const float* dxb = g_dx + ((size_t)i*NPIX + (size_t)n*HW)*DF;
    #pragma unroll
    for (int r = 0; r < 3; r++){
        int hh = h + (r-1)*d;
        if ((unsigned)hh < (unsigned)HH){
            #pragma unroll
            for (int j = 0; j < 2; j++){
                int w = t + 64*j;
                const float* src = dxb + (size_t)(hh*WWD + w)*DF;
                float4 v0 = *(const float4*)src;
                float4 v1 = *(const float4*)(src+4);
                xs[r][0][w]=v0.x; xs[r][1][w]=v0.y; xs[r][2][w]=v0.z; xs[r][3][w]=v0.w;
                xs[r][4][w]=v1.x; xs[r][5][w]=v1.y; xs[r][6][w]=v1.z; xs[r][7][w]=v1.w;
            }
        } else {
            for (int idx = t; idx < 8*128; idx += 64) (&xs[r][0][0])[idx] = 0.f;
        }
    }
    for (int idx = t; idx < 576; idx += 64){
        wsk[idx] = Kw[(size_t)i*576 + idx];
        wsq[idx] = Qw[(size_t)i*576 + idx];
        wsv[idx] = Vw[(size_t)i*576 + idx];
    }
    if (t < 8){ sbk[t]=Kb[i*8+t]; sbq[t]=Qb[i*8+t]; sbv[t]=Vb[i*8+t]; }
    __syncthreads();

    const int w0 = t, w1 = t + 64;
    float ak0[8], ak1[8], aq0[8], aq1[8], av0[8], av1[8];
    #pragma unroll
    for (int c=0;c<8;c++){ ak0[c]=ak1[c]=aq0[c]=aq1[c]=av0[c]=av1[c]=0.f; }

    #pragma unroll 1
    for (int tap = 0; tap < 9; tap++){
        int ky = tap/3, kx = tap%3;
        int c0 = w0 + (kx-1)*d; bool ok0 = (unsigned)c0 < (unsigned)WWD;
        int c1 = w1 + (kx-1)*d; bool ok1 = (unsigned)c1 < (unsigned)WWD;
        const float* xr = &xs[ky][0][0];
        #pragma unroll
        for (int ci = 0; ci < 8; ci++){
            float x0 = ok0 ? xr[ci*128 + c0] : 0.f;
            float x1 = ok1 ? xr[ci*128 + c1] : 0.f;
            const float* wk = &wsk[(tap*8+ci)*8];
            const float* wq = &wsq[(tap*8+ci)*8];
            const float* wv = &wsv[(tap*8+ci)*8];
            #pragma unroll
            for (int co = 0; co < 8; co++){
                ak0[co] += x0*wk[co]; ak1[co] += x1*wk[co];
                aq0[co] += x0*wq[co]; aq1[co] += x1*wq[co];
                av0[co] += x0*wv[co]; av1[co] += x1*wv[co];
            }
        }
    }

    float kq0[8], kq1[8], vv0[8], vv1[8];
    #pragma unroll
    for (int co = 0; co < 8; co++){
        float k0 = fmaxf(ak0[co]+sbk[co],0.f), k1 = fmaxf(ak1[co]+sbk[co],0.f);
        float q0 = fmaxf(aq0[co]+sbq[co],0.f), q1 = fmaxf(aq1[co]+sbq[co],0.f);
        vv0[co]  = fmaxf(av0[co]+sbv[co],0.f); vv1[co] = fmaxf(av1[co]+sbv[co],0.f);
        kq0[co] = k0*q0; kq1[co] = k1*q1;
    }
    const int in = i*NB + n;
    const int hwb = h*WWD;
    #pragma unroll
    for (int co = 0; co < 8; co++){
        float* kp = g_kq + ((size_t)in*DF + co)*HW + hwb;
        kp[w0] = kq0[co]; kp[w1] = kq1[co];
    }
    float* vp0 = g_v + ((size_t)i*NPIX + (size_t)n*HW + hwb + w0)*DF;
    float* vp1 = g_v + ((size_t)i*NPIX + (size_t)n*HW + hwb + w1)*DF;
    *(float4*)vp0     = make_float4(vv0[0],vv0[1],vv0[2],vv0[3]);
    *(float4*)(vp0+4) = make_float4(vv0[4],vv0[5],vv0[6],vv0[7]);
    *(float4*)vp1     = make_float4(vv1[0],vv1[1],vv1[2],vv1[3]);
    *(float4*)(vp1+4) = make_float4(vv1[4],vv1[5],vv1[6],vv1[7]);
}

// ---------------- K4: softmax stats ----------------
__global__ __launch_bounds__(256) void k_softstats(){
    const int plane = blockIdx.x;
    const float4* p = (const float4*)(g_kq + (size_t)plane*HW);
    const int t = threadIdx.x, lane = t & 31, warp = t >> 5;
    __shared__ float red[8];

    float m = -1e30f;
    for (int idx = t; idx < HW/4; idx += 256){
        float4 v = p[idx];
        m = fmaxf(m, fmaxf(fmaxf(v.x,v.y), fmaxf(v.z,v.w)));
    }
    #pragma unroll
    for (int o=16;o;o>>=1) m = fmaxf(m, __shfl_xor_sync(0xffffffffu, m, o));
    if (lane==0) red[warp] = m;
    __syncthreads();
    float bm = red[0];
    #pragma unroll
    for (int k=1;k<8;k++) bm = fmaxf(bm, red[k]);
    __syncthreads();

    float s = 0.f;
    for (int idx = t; idx < HW/4; idx += 256){
        float4 v = p[idx];
        s += __expf(v.x-bm) + __expf(v.y-bm) + __expf(v.z-bm) + __expf(v.w-bm);
    }
    #pragma unroll
    for (int o=16;o;o>>=1) s += __shfl_xor_sync(0xffffffffu, s, o);
    if (lane==0) red[warp] = s;
    __syncthreads();
    if (t == 0){
        float tot = 0.f;
        #pragma unroll
        for (int k=0;k<8;k++) tot += red[k];
        g_smax[plane] = bm;
        g_sinv[plane] = 1.0f / tot;
    }
}

// ---------------- K5: softmax*v + LN over DF -> fp16 cat channels ----------------
__global__ __launch_bounds__(256) void k_attn_ln(const float* __restrict__ gup, const float* __restrict__ bup){
    __shared__ float sm[8], si[8], sg[8], sb[8];
    const int in = blockIdx.y;
    const int t = threadIdx.x;
    if (t < 8){ sm[t]=g_smax[in*DF+t]; si[t]=g_sinv[in*DF+t]; sg[t]=gup[t]; sb[t]=bup[t]; }
    __syncthreads();
    const int hw = blockIdx.x*256 + t;
    const int i = in >> 2, n = in & 3;

    size_t vb = ((size_t)i*NPIX + (size_t)n*HW + hw)*DF;
    float4 v0 = *(const float4*)&g_v[vb];
    float4 v1 = *(const float4*)&g_v[vb+4];
    float vv[8] = {v0.x,v0.y,v0.z,v0.w,v1.x,v1.y,v1.z,v1.w};

    float y[8]; float s = 0.f;
    #pragma unroll
    for (int c = 0; c < 8; c++){
        float kq = g_kq[((size_t)in*DF + c)*HW + hw];
        float a = __expf(kq - sm[c]) * si[c];
        y[c] = a * vv[c];
        s += y[c];
    }
    float mean = s * 0.125f, q = 0.f;
    #pragma unroll
    for (int c = 0; c < 8; c++){ float dd = y[c]-mean; q += dd*dd; }
    float r = rsqrtf(q*0.125f + EPSF);
    float o[8];
    #pragma unroll
    for (int c = 0; c < 8; c++) o[c] = (y[c]-mean)*r*sg[c] + sb[c];

    size_t ob = ((size_t)(n*HW + hw))*CATC + CC + i*DF;
    store_h8(g_hf + ob, o);
}

// ---------------- K6: smooth 3x3 conv 384->256, HMMA fp16, split xn/attn, 2-buffer (R10) ----------------
#define BUF_BYTES 32768
#define K6_SMEM (1024 + 2*BUF_BYTES)

template<int NSTAGE, int CCDIV, int CCBASE, bool INITG, bool FINAL>
__global__ void __launch_bounds__(256, 2) k_smooth_part(const float* __restrict__ bias){
    extern __shared__ __align__(128) char smem[];
    float* s_bias = (float*)smem;
    const uint32_t sb0 = smem_u32(smem) + 1024;

    const int t = threadIdx.x;
    const int lane = t & 31, wid = t >> 5;
    const int wm = wid & 3, wn = wid >> 2;
    const int row_id = blockIdx.x;
    const int n = row_id >> 7, h = row_id & 127;
    const int oc0 = blockIdx.y * 128;

    if (FINAL && t < 128) s_bias[t] = bias[oc0 + t];

    const int srow = t >> 1;
    const int cb   = (t & 1) * 4;

    uint32_t dsw[4];
    #pragma unroll
    for (int j = 0; j < 4; j++){
        uint32_t off = (uint32_t)srow*128 + (uint32_t)(cb + j)*16;
        dsw[j] = off ^ ((off >> 3) & 0x70);
    }

    auto stage_issue = [&](int s, int b){
        const int tap = s / CCDIV, cc = CCBASE + (s % CCDIV) * 64;
        const int dy = tap/3 - 1, dxo = tap%3 - 1;
        const int hh = h + dy;
        const int ww = srow + dxo;
        const bool ok = ((unsigned)hh < (unsigned)HH) && ((unsigned)ww < (unsigned)WWD);
        const int hcl = ok ? hh : 0, wcl = ok ? ww : 0;
        const uint32_t sz = ok ? 16u : 0u;
        const uint32_t base = sb0 + (uint32_t)b*BUF_BYTES;
        const size_t abase = ((size_t)((n*HH + hcl)*WWD + wcl))*CATC + cc + cb*8;
        const size_t wbase = ((size_t)(tap*256 + oc0 + srow))*CATC + cc + cb*8;
        #pragma unroll
        for (int j = 0; j < 4; j++){
            cpa16(base +         dsw[j], g_hf + abase + j*8, sz);
            cpa16(base + 16384 + dsw[j], g_Wh + wbase + j*8, 16u);
        }
        CP_COMMIT();
    };

    const int pix0 = row_id * 128;
    float acc[2][8][4];
    if (INITG){
        #pragma unroll
        for (int mt = 0; mt < 2; mt++){
            #pragma unroll
            for (int nt = 0; nt < 8; nt++){
                int r = wm*32 + mt*16 + (lane >> 2);
                int cidx = wn*64 + nt*8 + (lane & 3)*2;
                float2 v0 = *(const float2*)(g_pre + (size_t)(pix0 + r)*CC + oc0 + cidx);
                float2 v1 = *(const float2*)(g_pre + (size_t)(pix0 + r + 8)*CC + oc0 + cidx);
                acc[mt][nt][0]=v0.x; acc[mt][nt][1]=v0.y; acc[mt][nt][2]=v1.x; acc[mt][nt][3]=v1.y;
            }
        }
    } else {
        #pragma unroll
        for (int a=0;a<2;a++)
            #pragma unroll
            for (int b=0;b<8;b++)
                #pragma unroll
                for (int c=0;c<4;c++) acc[a][b][c] = 0.f;
    }

    stage_issue(0, 0);

    #pragma unroll 1
    for (int s = 0; s < NSTAGE; s++){
        if (s + 1 < NSTAGE){
            stage_issue(s + 1, (s + 1) & 1);
            CP_WAIT1();
        } else {
            CP_WAIT0();
        }
        __syncthreads();

        const uint32_t base = sb0 + (uint32_t)(s & 1)*BUF_BYTES;
        const uint32_t aB = base, bB = base + 16384;

        #pragma unroll
        for (int ks = 0; ks < 4; ks++){
            uint32_t ah[2][4];
            #pragma unroll
            for (int mt = 0; mt < 2; mt++){
                uint32_t arow = (uint32_t)(wm*32 + mt*16 + (lane & 15));
                uint32_t ac16 = (uint32_t)(ks*2 + (lane >> 4));
                uint32_t off = arow*128 + ac16*16;
                uint32_t sw = off ^ ((off >> 3) & 0x70);
                ldsm4(ah[mt], aB + sw);
            }
            uint32_t brow = (uint32_t)(wn*64 + ((lane >> 4) << 3) + (lane & 7));
            uint32_t bc16 = (uint32_t)(ks*2 + ((lane >> 3) & 1));
            #pragma unroll
            for (int g = 0; g < 4; g++){
                uint32_t off = (brow + (uint32_t)g*16)*128 + bc16*16;
                uint32_t sw = off ^ ((off >> 3) & 0x70);
                uint32_t bfr[4];
                ldsm4(bfr, bB + sw);
                mma16816h(acc[0][2*g],   ah[0], bfr);
                mma16816h(acc[1][2*g],   ah[1], bfr);
                mma16816h(acc[0][2*g+1], ah[0], bfr+2);
                mma16816h(acc[1][2*g+1], ah[1], bfr+2);
            }
        }
        __syncthreads();
    }

    // Epilogue
    #pragma unroll
    for (int mt = 0; mt < 2; mt++){
        #pragma unroll
        for (int nt = 0; nt < 8; nt++){
            int r = wm*32 + mt*16 + (lane >> 2);
            int cidx = wn*64 + nt*8 + (lane & 3)*2;
            float* p0 = g_pre + (size_t)(pix0 + r)*CC + oc0 + cidx;
            float* p1 = g_pre + (size_t)(pix0 + r + 8)*CC + oc0 + cidx;
            if (FINAL){
                float b0 = s_bias[cidx], b1 = s_bias[cidx+1];
                *(float2*)p0 = make_float2(fmaxf(acc[mt][nt][0]+b0, 0.f), fmaxf(acc[mt][nt][1]+b1, 0.f));
                *(float2*)p1 = make_float2(fmaxf(acc[mt][nt][2]+b0, 0.f), fmaxf(acc[mt][nt][3]+b1, 0.f));
            } else {
                *(float2*)p0 = make_float2(acc[mt][nt][0], acc[mt][nt][1]);
                *(float2*)p1 = make_float2(acc[mt][nt][2], acc[mt][nt][3]);
            }
        }
    }
}

// ---------------- launch ----------------
extern "C" void kernel_launch(void* const* d_in, const int* in_sizes, int n_in,
                              void* d_out, int out_size){
    (void)in_sizes; (void)n_in; (void)out_size;
    const float* x        = (const float*)d_in[0];
    const float* dwn_w    = (const float*)d_in[1];
    const float* dwn_b    = (const float*)d_in[2];
    const float* k_w      = (const float*)d_in[3];
    const float* k_b      = (const float*)d_in[4];
    const float* q_w      = (const float*)d_in[5];
    const float* q_b      = (const float*)d_in[6];
    const float* v_w      = (const float*)d_in[7];
    const float* v_b      = (const float*)d_in[8];
    const float* smooth_w = (const float*)d_in[9];
    const float* smooth_b = (const float*)d_in[10];
    const float* ln_in_g  = (const float*)d_in[11];
    const float* ln_in_b  = (const float*)d_in[12];
    const float* ln_up_g  = (const float*)d_in[13];
    const float* ln_up_b  = (const float*)d_in[14];
    const float* ln_out_g = (const float*)d_in[15];
    const float* ln_out_b = (const float*)d_in[16];
    float* out = (float*)d_out;

    cudaFuncSetAttribute(k_smooth_part<36,4,0,false,false>,
                         cudaFuncAttributeMaxDynamicSharedMemorySize, K6_SMEM);
    cudaFuncSetAttribute(k_smooth_part<18,2,256,true,true>,
                         cudaFuncAttributeMaxDynamicSharedMemorySize, K6_SMEM);

    // fork: s1 joins capture via event recorded on origin stream first
    cudaEventRecord(g_sk.eFork, 0);
    cudaStreamWaitEvent(g_sk.s1, g_sk.eFork, 0);

    // s1 (HIGH prio, critical path): weight prep, then p1 after ln_in's data is ready
    k_wprep<<<9*384, 256, 0, g_sk.s1>>>(smooth_w);

    // origin: input LN
    k_ln_in<<<NPIX/8, 256>>>(x, ln_in_g, ln_in_b);
    cudaEventRecord(g_sk.eL, 0);

    // s1: p1 (xn-part of smooth conv) — needs g_hf[0..255] (eL) + g_Wh (in-stream after wprep)
    cudaStreamWaitEvent(g_sk.s1, g_sk.eL, 0);
    k_smooth_part<36,4,0,false,false><<<dim3(NB*HH, 2), 256, K6_SMEM, g_sk.s1>>>(smooth_b);
    cudaEventRecord(g_sk.eP1, g_sk.s1);

    // origin (default prio, slack path): attention chain — ordered after ln_in in-stream
    k_dwn<<<dim3(NDIL/2, NPIX/1024), 256>>>(dwn_w, dwn_b);
    k_kqv<<<dim3(HH, NB, NDIL), 64>>>(k_w, k_b, q_w, q_b, v_w, v_b);
    k_softstats<<<NDIL*NB*DF, 256>>>();
    k_attn_ln<<<dim3(HW/256, NDIL*NB), 256>>>(ln_up_g, ln_up_b);

    // join on origin: p2 needs chain (in-stream) + p1 (eP1)
    cudaStreamWaitEvent(0, g_sk.eP1, 0);
    k_smooth_part<18,2,256,true,true><<<dim3(NB*HH, 2), 256, K6_SMEM>>>(smooth_b);
    k_ln_out<<<NPIX/8, 256>>>(ln_out_g, ln_out_b, out);
}

// round 16
// speedup vs baseline: 1.1617x; 1.0320x over previous
#include <cuda_runtime.h>
#include <cuda_fp16.h>
#include <cstdint>

#define NB 4
#define HH 128
#define WWD 128
#define CC 256
#define NDIL 16
#define DF 8
#define CATC 384
#define HW (HH*WWD)
#define NPIX (NB*HW)
#define EPSF 1e-3f

// ---------------- scratch (static device globals: allocation-free) ----------------
__device__ float g_x32[(size_t)NPIX*CC];
__device__ __half g_hf[(size_t)NPIX*CATC];
__device__ float g_dx [(size_t)NDIL*NPIX*DF];
__device__ float g_kq [(size_t)NDIL*NB*DF*HW];
__device__ float g_v  [(size_t)NDIL*NPIX*DF];
__device__ float g_pre[(size_t)NPIX*CC];
__device__ float g_smax[NDIL*NB*DF];
__device__ float g_sinv[NDIL*NB*DF];
__device__ __half g_Wh[(size_t)9*256*384];

// ---------------- stream kit ----------------
namespace {
struct StreamKit {
    cudaStream_t s1;
    cudaEvent_t eFork, eD, eP1;
    StreamKit(){
        int lo = 0, hi = 0;
        cudaDeviceGetStreamPriorityRange(&lo, &hi);   // hi = highest priority
        cudaStreamCreateWithPriority(&s1, cudaStreamNonBlocking, hi);
        cudaEventCreateWithFlags(&eFork, cudaEventDisableTiming);
        cudaEventCreateWithFlags(&eD,    cudaEventDisableTiming);
        cudaEventCreateWithFlags(&eP1,   cudaEventDisableTiming);
    }
};
StreamKit g_sk;
}

// ---------------- f32x2 helpers ----------------
__device__ __forceinline__ unsigned long long dup2(float f){
    unsigned long long r; unsigned u = __float_as_uint(f);
    asm("mov.b64 %0, {%1, %1};" : "=l"(r) : "r"(u));
    return r;
}
__device__ __forceinline__ unsigned long long ffma2(unsigned long long a, unsigned long long b, unsigned long long c){
    unsigned long long d;
    asm("fma.rn.f32x2 %0, %1, %2, %3;" : "=l"(d) : "l"(a), "l"(b), "l"(c));
    return d;
}
__device__ __forceinline__ float2 unpk(unsigned long long v){
    unsigned lo, hi;
    asm("mov.b64 {%0, %1}, %2;" : "=r"(lo), "=r"(hi) : "l"(v));
    return make_float2(__uint_as_float(lo), __uint_as_float(hi));
}

// ---------------- warp MMA + cp.async plumbing ----------------
__device__ __forceinline__ uint32_t smem_u32(const void* p){
    uint32_t a;
    asm("{ .reg .u64 t; cvta.to.shared.u64 t, %1; cvt.u32.u64 %0, t; }" : "=r"(a) : "l"(p));
    return a;
}
__device__ __forceinline__ void ldsm4(uint32_t* r, uint32_t addr){
    asm volatile("ldmatrix.sync.aligned.m8n8.x4.shared.b16 {%0,%1,%2,%3}, [%4];"
        : "=r"(r[0]), "=r"(r[1]), "=r"(r[2]), "=r"(r[3]) : "r"(addr));
}
__device__ __forceinline__ void mma16816h(float* c, const uint32_t* a, const uint32_t* b){
    asm volatile("mma.sync.aligned.m16n8k16.row.col.f32.f16.f16.f32 "
        "{%0,%1,%2,%3}, {%4,%5,%6,%7}, {%8,%9}, {%0,%1,%2,%3};"
        : "+f"(c[0]), "+f"(c[1]), "+f"(c[2]), "+f"(c[3])
        : "r"(a[0]), "r"(a[1]), "r"(a[2]), "r"(a[3]), "r"(b[0]), "r"(b[1]));
}
__device__ __forceinline__ void cpa16(uint32_t dst, const void* src, uint32_t srcsize){
    asm volatile("cp.async.cg.shared.global [%0], [%1], 16, %2;"
        :: "r"(dst), "l"(src), "r"(srcsize) : "memory");
}
#define CP_COMMIT() asm volatile("cp.async.commit_group;" ::: "memory")
#define CP_WAIT1()  asm volatile("cp.async.wait_group 1;" ::: "memory")
#define CP_WAIT0()  asm volatile("cp.async.wait_group 0;" ::: "memory")

__device__ __forceinline__ void store_h8(__half* hp, const float* v){
    __half hh[8];
    #pragma unroll
    for (int j=0;j<8;j++) hh[j] = __float2half_rn(v[j]);
    *(uint4*)hp = *(uint4*)hh;
}

// ---------------- K0: weight prep ----------------
__global__ __launch_bounds__(256) void k_wprep(const float* __restrict__ W){
    int idx = blockIdx.x*256 + threadIdx.x;
    int oc = idx & 255;
    int rest = idx >> 8;
    int ch = rest % 384, tap = rest / 384;
    float w = W[idx];
    size_t o = ((size_t)(tap*256 + oc))*384 + ch;
    g_Wh[o] = __float2half_rn(w);
}

// ---------------- K1: input LayerNorm ----------------
__global__ __launch_bounds__(256) void k_ln_in(const float* __restrict__ x,
                                               const float* __restrict__ gg, const float* __restrict__ bb){
    int gw = (blockIdx.x*blockDim.x + threadIdx.x) >> 5;
    int lane = threadIdx.x & 31;
    if (gw >= NPIX) return;
    const float4* sp = (const float4*)(x + (size_t)gw*CC);
    float4 a0 = sp[lane*2], a1 = sp[lane*2+1];
    float s = a0.x+a0.y+a0.z+a0.w + a1.x+a1.y+a1.z+a1.w;
    #pragma unroll
    for (int o=16;o;o>>=1) s += __shfl_xor_sync(0xffffffffu, s, o);
    float m = s * (1.0f/256.0f);
    float d[8] = {a0.x-m,a0.y-m,a0.z-m,a0.w-m,a1.x-m,a1.y-m,a1.z-m,a1.w-m};
    float q = 0.f;
    #pragma unroll
    for (int j=0;j<8;j++) q += d[j]*d[j];
    #pragma unroll
    for (int o=16;o;o>>=1) q += __shfl_xor_sync(0xffffffffu, q, o);
    float r = rsqrtf(q*(1.0f/256.0f) + EPSF);
    const float4* gp = (const float4*)gg; const float4* bp = (const float4*)bb;
    float4 g0 = gp[lane*2], g1 = gp[lane*2+1];
    float4 b0 = bp[lane*2], b1 = bp[lane*2+1];
    float gv[8] = {g0.x,g0.y,g0.z,g0.w,g1.x,g1.y,g1.z,g1.w};
    float bv[8] = {b0.x,b0.y,b0.z,b0.w,b1.x,b1.y,b1.z,b1.w};
    float o[8];
    #pragma unroll
    for (int j=0;j<8;j++) o[j] = d[j]*r*gv[j] + bv[j];
    float* dp = g_x32 + (size_t)gw*CC + lane*8;
    *(float4*)dp = make_float4(o[0],o[1],o[2],o[3]);
    *(float4*)(dp+4) = make_float4(o[4],o[5],o[6],o[7]);
    store_h8(g_hf + (size_t)gw*CATC + lane*8, o);
}

// ---------------- output LayerNorm over 256 channels ----------------
__global__ __launch_bounds__(256) void k_ln_out(const float* __restrict__ gg, const float* __restrict__ bb,
                                                float* __restrict__ out){
    int gw = (blockIdx.x*blockDim.x + threadIdx.x) >> 5;
    int lane = threadIdx.x & 31;
    if (gw >= NPIX) return;
    const float4* sp = (const float4*)(g_pre + (size_t)gw*CC);
    float4 a0 = sp[lane*2], a1 = sp[lane*2+1];
    float s = a0.x+a0.y+a0.z+a0.w + a1.x+a1.y+a1.z+a1.w;
    #pragma unroll
    for (int o=16;o;o>>=1) s += __shfl_xor_sync(0xffffffffu, s, o);
    float m = s * (1.0f/256.0f);
    float d0=a0.x-m, d1=a0.y-m, d2=a0.z-m, d3=a0.w-m;
    float d4=a1.x-m, d5=a1.y-m, d6=a1.z-m, d7=a1.w-m;
    float q = d0*d0+d1*d1+d2*d2+d3*d3+d4*d4+d5*d5+d6*d6+d7*d7;
    #pragma unroll
    for (int o=16;o;o>>=1) q += __shfl_xor_sync(0xffffffffu, q, o);
    float r = rsqrtf(q*(1.0f/256.0f) + EPSF);
    const float4* gp = (const float4*)gg; const float4* bp = (const float4*)bb;
    float4 g0 = gp[lane*2], g1 = gp[lane*2+1];
    float4 b0 = bp[lane*2], b1 = bp[lane*2+1];
    float4 o0 = make_float4(d0*r*g0.x+b0.x, d1*r*g0.y+b0.y, d2*r*g0.z+b0.z, d3*r*g0.w+b0.w);
    float4 o1 = make_float4(d4*r*g1.x+b1.x, d5*r*g1.y+b1.y, d6*r*g1.z+b1.z, d7*r*g1.w+b1.w);
    float* dp = out + (size_t)gw*CC + lane*8;
    *(float4*)dp = o0;
    *(float4*)(dp+4) = o1;
}

// ---------------- K2: 1x1 down conv (256 -> 8), 4 branches per CTA, relu, f32x2 ----------------
// grid (NDIL/4, NPIX/512). 512-px chunks, 2 px/thread. 4x reuse of g_x32 chunk via co-scheduled CTAs.
__global__ __launch_bounds__(256) void k_dwn(const float* __restrict__ Wd, const float* __restrict__ Bd){
    __shared__ __align__(16) float ws[4*CC*DF];   // 32 KB (four branches)
    __shared__ float xs[8][512];                  // 16 KB chunk [c][p]
    const int i0 = blockIdx.x * 4;
    const int px0 = blockIdx.y * 512;
    const int t = threadIdx.x;

    const float4* wsrc = (const float4*)(Wd + (size_t)i0*CC*DF);
    for (int idx = t; idx < 4*CC*DF/4; idx += 256) ((float4*)ws)[idx] = wsrc[idx];

    unsigned long long acc[4][2][4];
    #pragma unroll
    for (int br=0;br<4;br++)
        #pragma unroll
        for (int j=0;j<2;j++)
            #pragma unroll
            for (int k=0;k<4;k++) acc[br][j][k] = 0ull;

    for (int cc = 0; cc < CC; cc += 8){
        __syncthreads();
        #pragma unroll
        for (int j = 0; j < 2; j++){
            int p = t + 256*j;
            const float* src = g_x32 + (size_t)(px0 + p)*CC + cc;
            float4 v0 = *(const float4*)src;
            float4 v1 = *(const float4*)(src+4);
            xs[0][p]=v0.x; xs[1][p]=v0.y; xs[2][p]=v0.z; xs[3][p]=v0.w;
            xs[4][p]=v1.x; xs[5][p]=v1.y; xs[6][p]=v1.z; xs[7][p]=v1.w;
        }
        __syncthreads();
        #pragma unroll
        for (int c = 0; c < 8; c++){
            unsigned long long xd0 = dup2(xs[c][t]), xd1 = dup2(xs[c][t+256]);
            #pragma unroll
            for (int br = 0; br < 4; br++){
                const unsigned long long* wp = (const unsigned long long*)&ws[br*CC*DF + (cc+c)*8];
                unsigned long long w0=wp[0], w1=wp[1], w2=wp[2], w3=wp[3];
                acc[br][0][0]=ffma2(xd0,w0,acc[br][0][0]); acc[br][0][1]=ffma2(xd0,w1,acc[br][0][1]);
                acc[br][0][2]=ffma2(xd0,w2,acc[br][0][2]); acc[br][0][3]=ffma2(xd0,w3,acc[br][0][3]);
                acc[br][1][0]=ffma2(xd1,w0,acc[br][1][0]); acc[br][1][1]=ffma2(xd1,w1,acc[br][1][1]);
                acc[br][1][2]=ffma2(xd1,w2,acc[br][1][2]); acc[br][1][3]=ffma2(xd1,w3,acc[br][1][3]);
            }
        }
    }
    #pragma unroll
    for (int br = 0; br < 4; br++){
        float bb[8];
        #pragma unroll
        for (int oc=0;oc<8;oc++) bb[oc] = Bd[(i0+br)*8+oc];
        #pragma unroll
        for (int j=0;j<2;j++){
            int p = px0 + t + 256*j;
            float o[8];
            #pragma unroll
            for (int k=0;k<4;k++){
                float2 f = unpk(acc[br][j][k]);
                o[2*k]   = fmaxf(f.x + bb[2*k],   0.f);
                o[2*k+1] = fmaxf(f.y + bb[2*k+1], 0.f);
            }
            float* dp = g_dx + ((size_t)(i0+br)*NPIX + p)*DF;
            *(float4*)dp     = make_float4(o[0],o[1],o[2],o[3]);
            *(float4*)(dp+4) = make_float4(o[4],o[5],o[6],o[7]);
        }
    }
}

// ---------------- K3: k,q,v 3x3 dilated convs + relu + kq product ----------------
__global__ __launch_bounds__(64) void k_kqv(const float* __restrict__ Kw, const float* __restrict__ Kb,
                                            const float* __restrict__ Qw, const float* __restrict__ Qb,
                                            const float* __restrict__ Vw, const float* __restrict__ Vb){
    __shared__ float xs[3][8][128];
    __shared__ float wsk[576], wsq[576], wsv[576];
    __shared__ float sbk[8], sbq[8], sbv[8];

    const int h = blockIdx.x, n = blockIdx.y, i = blockIdx.z;
    const int d = i + 1;
    const int t = threadIdx.x;

    const float* dxb = g_dx + ((size_t)i*NPIX + (size_t)n*HW)*DF;
    #pragma unroll
    for (int r = 0; r < 3; r++){
        int hh = h + (r-1)*d;
        if ((unsigned)hh < (unsigned)HH){
            #pragma unroll
            for (int j = 0; j < 2; j++){
                int w = t + 64*j;
                const float* src = dxb + (size_t)(hh*WWD + w)*DF;
                float4 v0 = *(const float4*)src;
                float4 v1 = *(const float4*)(src+4);
                xs[r][0][w]=v0.x; xs[r][1][w]=v0.y; xs[r][2][w]=v0.z; xs[r][3][w]=v0.w;
                xs[r][4][w]=v1.x; xs[r][5][w]=v1.y; xs[r][6][w]=v1.z; xs[r][7][w]=v1.w;
            }
        } else {
            for (int idx = t; idx < 8*128; idx += 64) (&xs[r][0][0])[idx] = 0.f;
        }
    }
    for (int idx = t; idx < 576; idx += 64){
        wsk[idx] = Kw[(size_t)i*576 + idx];
        wsq[idx] = Qw[(size_t)i*576 + idx];
        wsv[idx] = Vw[(size_t)i*576 + idx];
    }
    if (t < 8){ sbk[t]=Kb[i*8+t]; sbq[t]=Qb[i*8+t]; sbv[t]=Vb[i*8+t]; }
    __syncthreads();

    const int w0 = t, w1 = t + 64;
    float ak0[8], ak1[8], aq0[8], aq1[8], av0[8], av1[8];
    #pragma unroll
    for (int c=0;c<8;c++){ ak0[c]=ak1[c]=aq0[c]=aq1[c]=av0[c]=av1[c]=0.f; }

    #pragma unroll 1
    for (int tap = 0; tap < 9; tap++){
        int ky = tap/3, kx = tap%3;
        int c0 = w0 + (kx-1)*d; bool ok0 = (unsigned)c0 < (unsigned)WWD;
        int c1 = w1 + (kx-1)*d; bool ok1 = (unsigned)c1 < (unsigned)WWD;
        const float* xr = &xs[ky][0][0];
        #pragma unroll
        for (int ci = 0; ci < 8; ci++){
            float x0 = ok0 ? xr[ci*128 + c0] : 0.f;
            float x1 = ok1 ? xr[ci*128 + c1] : 0.f;
            const float* wk = &wsk[(tap*8+ci)*8];
            const float* wq = &wsq[(tap*8+ci)*8];
            const float* wv = &wsv[(tap*8+ci)*8];
            #pragma unroll
            for (int co = 0; co < 8; co++){
                ak0[co] += x0*wk[co]; ak1[co] += x1*wk[co];
                aq0[co] += x0*wq[co]; aq1[co] += x1*wq[co];
                av0[co] += x0*wv[co]; av1[co] += x1*wv[co];
            }
        }
    }

    float kq0[8], kq1[8], vv0[8], vv1[8];
    #pragma unroll
    for (int co = 0; co < 8; co++){
        float k0 = fmaxf(ak0[co]+sbk[co],0.f), k1 = fmaxf(ak1[co]+sbk[co],0.f);
        float q0 = fmaxf(aq0[co]+sbq[co],0.f), q1 = fmaxf(aq1[co]+sbq[co],0.f);
        vv0[co]  = fmaxf(av0[co]+sbv[co],0.f); vv1[co] = fmaxf(av1[co]+sbv[co],0.f);
        kq0[co] = k0*q0; kq1[co] = k1*q1;
    }
    const int in = i*NB + n;
    const int hwb = h*WWD;
    #pragma unroll
    for (int co = 0; co < 8; co++){
        float* kp = g_kq + ((size_t)in*DF + co)*HW + hwb;
        kp[w0] = kq0[co]; kp[w1] = kq1[co];
    }
    float* vp0 = g_v + ((size_t)i*NPIX + (size_t)n*HW + hwb + w0)*DF;
    float* vp1 = g_v + ((size_t)i*NPIX + (size_t)n*HW + hwb + w1)*DF;
    *(float4*)vp0     = make_float4(vv0[0],vv0[1],vv0[2],vv0[3]);
    *(float4*)(vp0+4) = make_float4(vv0[4],vv0[5],vv0[6],vv0[7]);
    *(float4*)vp1     = make_float4(vv1[0],vv1[1],vv1[2],vv1[3]);
    *(float4*)(vp1+4) = make_float4(vv1[4],vv1[5],vv1[6],vv1[7]);
}

// ---------------- K4: softmax stats ----------------
__global__ __launch_bounds__(256) void k_softstats(){
    const int plane = blockIdx.x;
    const float4* p = (const float4*)(g_kq + (size_t)plane*HW);
    const int t = threadIdx.x, lane = t & 31, warp = t >> 5;
    __shared__ float red[8];

    float m = -1e30f;
    for (int idx = t; idx < HW/4; idx += 256){
        float4 v = p[idx];
        m = fmaxf(m, fmaxf(fmaxf(v.x,v.y), fmaxf(v.z,v.w)));
    }
    #pragma unroll
    for (int o=16;o;o>>=1) m = fmaxf(m, __shfl_xor_sync(0xffffffffu, m, o));
    if (lane==0) red[warp] = m;
    __syncthreads();
    float bm = red[0];
    #pragma unroll
    for (int k=1;k<8;k++) bm = fmaxf(bm, red[k]);
    __syncthreads();

    float s = 0.f;
    for (int idx = t; idx < HW/4; idx += 256){
        float4 v = p[idx];
        s += __expf(v.x-bm) + __expf(v.y-bm) + __expf(v.z-bm) + __expf(v.w-bm);
    }
    #pragma unroll
    for (int o=16;o;o>>=1) s += __shfl_xor_sync(0xffffffffu, s, o);
    if (lane==0) red[warp] = s;
    __syncthreads();
    if (t == 0){
        float tot = 0.f;
        #pragma unroll
        for (int k=0;k<8;k++) tot += red[k];
        g_smax[plane] = bm;
        g_sinv[plane] = 1.0f / tot;
    }
}

// ---------------- K5: softmax*v + LN over DF -> fp16 cat channels ----------------
__global__ __launch_bounds__(256) void k_attn_ln(const float* __restrict__ gup, const float* __restrict__ bup){
    __shared__ float sm[8], si[8], sg[8], sb[8];
    const int in = blockIdx.y;
    const int t = threadIdx.x;
    if (t < 8){ sm[t]=g_smax[in*DF+t]; si[t]=g_sinv[in*DF+t]; sg[t]=gup[t]; sb[t]=bup[t]; }
    __syncthreads();
    const int hw = blockIdx.x*256 + t;
    const int i = in >> 2, n = in & 3;

    size_t vb = ((size_t)i*NPIX + (size_t)n*HW + hw)*DF;
    float4 v0 = *(const float4*)&g_v[vb];
    float4 v1 = *(const float4*)&g_v[vb+4];
    float vv[8] = {v0.x,v0.y,v0.z,v0.w,v1.x,v1.y,v1.z,v1.w};

    float y[8]; float s = 0.f;
    #pragma unroll
    for (int c = 0; c < 8; c++){
        float kq = g_kq[((size_t)in*DF + c)*HW + hw];
        float a = __expf(kq - sm[c]) * si[c];
        y[c] = a * vv[c];
        s += y[c];
    }
    float mean = s * 0.125f, q = 0.f;
    #pragma unroll
    for (int c = 0; c < 8; c++){ float dd = y[c]-mean; q += dd*dd; }
    float r = rsqrtf(q*0.125f + EPSF);
    float o[8];
    #pragma unroll
    for (int c = 0; c < 8; c++) o[c] = (y[c]-mean)*r*sg[c] + sb[c];

    size_t ob = ((size_t)(n*HW + hw))*CATC + CC + i*DF;
    store_h8(g_hf + ob, o);
}

// ---------------- K6: smooth 3x3 conv 384->256, HMMA fp16, split xn/attn, 2-buffer ----------------
#define BUF_BYTES 32768
#define K6_SMEM (1024 + 2*BUF_BYTES)

template<int NSTAGE, int CCDIV, int CCBASE, bool INITG, bool FINAL>
__global__ void __launch_bounds__(256, 2) k_smooth_part(const float* __restrict__ bias){
    extern __shared__ __align__(128) char smem[];
    float* s_bias = (float*)smem;
    const uint32_t sb0 = smem_u32(smem) + 1024;

    const int t = threadIdx.x;
    const int lane = t & 31, wid = t >> 5;
    const int wm = wid & 3, wn = wid >> 2;
    const int row_id = blockIdx.x;
    const int n = row_id >> 7, h = row_id & 127;
    const int oc0 = blockIdx.y * 128;

    if (FINAL && t < 128) s_bias[t] = bias[oc0 + t];

    const int srow = t >> 1;
    const int cb   = (t & 1) * 4;

    uint32_t dsw[4];
    #pragma unroll
    for (int j = 0; j < 4; j++){
        uint32_t off = (uint32_t)srow*128 + (uint32_t)(cb + j)*16;
        dsw[j] = off ^ ((off >> 3) & 0x70);
    }

    auto stage_issue = [&](int s, int b){
        const int tap = s / CCDIV, cc = CCBASE + (s % CCDIV) * 64;
        const int dy = tap/3 - 1, dxo = tap%3 - 1;
        const int hh = h + dy;
        const int ww = srow + dxo;
        const bool ok = ((unsigned)hh < (unsigned)HH) && ((unsigned)ww < (unsigned)WWD);
        const int hcl = ok ? hh : 0, wcl = ok ? ww : 0;
        const uint32_t sz = ok ? 16u : 0u;
        const uint32_t base = sb0 + (uint32_t)b*BUF_BYTES;
        const size_t abase = ((size_t)((n*HH + hcl)*WWD + wcl))*CATC + cc + cb*8;
        const size_t wbase = ((size_t)(tap*256 + oc0 + srow))*CATC + cc + cb*8;
        #pragma unroll
        for (int j = 0; j < 4; j++){
            cpa16(base +         dsw[j], g_hf + abase + j*8, sz);
            cpa16(base + 16384 + dsw[j], g_Wh + wbase + j*8, 16u);
        }
        CP_COMMIT();
    };

    const int pix0 = row_id * 128;
    float acc[2][8][4];
    if (INITG){
        #pragma unroll
        for (int mt = 0; mt < 2; mt++){
            #pragma unroll
            for (int nt = 0; nt < 8; nt++){
                int r = wm*32 + mt*16 + (lane >> 2);
                int cidx = wn*64 + nt*8 + (lane & 3)*2;
                float2 v0 = *(const float2*)(g_pre + (size_t)(pix0 + r)*CC + oc0 + cidx);
                float2 v1 = *(const float2*)(g_pre + (size_t)(pix0 + r + 8)*CC + oc0 + cidx);
                acc[mt][nt][0]=v0.x; acc[mt][nt][1]=v0.y; acc[mt][nt][2]=v1.x; acc[mt][nt][3]=v1.y;
            }
        }
    } else {
        #pragma unroll
        for (int a=0;a<2;a++)
            #pragma unroll
            for (int b=0;b<8;b++)
                #pragma unroll
                for (int c=0;c<4;c++) acc[a][b][c] = 0.f;
    }

    stage_issue(0, 0);

    #pragma unroll 1
    for (int s = 0; s < NSTAGE; s++){
        if (s + 1 < NSTAGE){
            stage_issue(s + 1, (s + 1) & 1);
            CP_WAIT1();
        } else {
            CP_WAIT0();
        }
        __syncthreads();

        const uint32_t base = sb0 + (uint32_t)(s & 1)*BUF_BYTES;
        const uint32_t aB = base, bB = base + 16384;

        #pragma unroll
        for (int ks = 0; ks < 4; ks++){
            uint32_t ah[2][4];
            #pragma unroll
            for (int mt = 0; mt < 2; mt++){
                uint32_t arow = (uint32_t)(wm*32 + mt*16 + (lane & 15));
                uint32_t ac16 = (uint32_t)(ks*2 + (lane >> 4));
                uint32_t off = arow*128 + ac16*16;
                uint32_t sw = off ^ ((off >> 3) & 0x70);
                ldsm4(ah[mt], aB + sw);
            }
            uint32_t brow = (uint32_t)(wn*64 + ((lane >> 4) << 3) + (lane & 7));
            uint32_t bc16 = (uint32_t)(ks*2 + ((lane >> 3) & 1));
            #pragma unroll
            for (int g = 0; g < 4; g++){
                uint32_t off = (brow + (uint32_t)g*16)*128 + bc16*16;
                uint32_t sw = off ^ ((off >> 3) & 0x70);
                uint32_t bfr[4];
                ldsm4(bfr, bB + sw);
                mma16816h(acc[0][2*g],   ah[0], bfr);
                mma16816h(acc[1][2*g],   ah[1], bfr);
                mma16816h(acc[0][2*g+1], ah[0], bfr+2);
                mma16816h(acc[1][2*g+1], ah[1], bfr+2);
            }
        }
        __syncthreads();
    }

    // Epilogue
    #pragma unroll
    for (int mt = 0; mt < 2; mt++){
        #pragma unroll
        for (int nt = 0; nt < 8; nt++){
            int r = wm*32 + mt*16 + (lane >> 2);
            int cidx = wn*64 + nt*8 + (lane & 3)*2;
            float* p0 = g_pre + (size_t)(pix0 + r)*CC + oc0 + cidx;
            float* p1 = g_pre + (size_t)(pix0 + r + 8)*CC + oc0 + cidx;
            if (FINAL){
                float b0 = s_bias[cidx], b1 = s_bias[cidx+1];
                *(float2*)p0 = make_float2(fmaxf(acc[mt][nt][0]+b0, 0.f), fmaxf(acc[mt][nt][1]+b1, 0.f));
                *(float2*)p1 = make_float2(fmaxf(acc[mt][nt][2]+b0, 0.f), fmaxf(acc[mt][nt][3]+b1, 0.f));
            } else {
                *(float2*)p0 = make_float2(acc[mt][nt][0], acc[mt][nt][1]);
                *(float2*)p1 = make_float2(acc[mt][nt][2], acc[mt][nt][3]);
            }
        }
    }
}

// ---------------- launch ----------------
extern "C" void kernel_launch(void* const* d_in, const int* in_sizes, int n_in,
                              void* d_out, int out_size){
    (void)in_sizes; (void)n_in; (void)out_size;
    const float* x        = (const float*)d_in[0];
    const float* dwn_w    = (const float*)d_in[1];
    const float* dwn_b    = (const float*)d_in[2];
    const float* k_w      = (const float*)d_in[3];
    const float* k_b      = (const float*)d_in[4];
    const float* q_w      = (const float*)d_in[5];
    const float* q_b      = (const float*)d_in[6];
    const float* v_w      = (const float*)d_in[7];
    const float* v_b      = (const float*)d_in[8];
    const float* smooth_w = (const float*)d_in[9];
    const float* smooth_b = (const float*)d_in[10];
    const float* ln_in_g  = (const float*)d_in[11];
    const float* ln_in_b  = (const float*)d_in[12];
    const float* ln_up_g  = (const float*)d_in[13];
    const float* ln_up_b  = (const float*)d_in[14];
    const float* ln_out_g = (const float*)d_in[15];
    const float* ln_out_b = (const float*)d_in[16];
    float* out = (float*)d_out;

    cudaFuncSetAttribute(k_smooth_part<36,4,0,false,false>,
                         cudaFuncAttributeMaxDynamicSharedMemorySize, K6_SMEM);
    cudaFuncSetAttribute(k_smooth_part<18,2,256,true,true>,
                         cudaFuncAttributeMaxDynamicSharedMemorySize, K6_SMEM);

    // fork: s1 joins capture via event recorded on origin stream first
    cudaEventRecord(g_sk.eFork, 0);
    cudaStreamWaitEvent(g_sk.s1, g_sk.eFork, 0);

    // s1 (HIGH prio): weight prep runs concurrent with ln_in + dwn
    k_wprep<<<9*384, 256, 0, g_sk.s1>>>(smooth_w);

    // origin: input LN, then down-conv at full machine speed (solo)
    k_ln_in<<<NPIX/8, 256>>>(x, ln_in_g, ln_in_b);
    k_dwn<<<dim3(NDIL/4, NPIX/512), 256>>>(dwn_w, dwn_b);
    cudaEventRecord(g_sk.eD, 0);

    // s1: p1 (xn-part of smooth conv) — after dwn completes (serialize heavy DRAM phases)
    cudaStreamWaitEvent(g_sk.s1, g_sk.eD, 0);
    k_smooth_part<36,4,0,false,false><<<dim3(NB*HH, 2), 256, K6_SMEM, g_sk.s1>>>(smooth_b);
    cudaEventRecord(g_sk.eP1, g_sk.s1);

    // origin (default prio, slack path): rest of attention chain, overlapping p1
    k_kqv<<<dim3(HH, NB, NDIL), 64>>>(k_w, k_b, q_w, q_b, v_w, v_b);
    k_softstats<<<NDIL*NB*DF, 256>>>();
    k_attn_ln<<<dim3(HW/256, NDIL*NB), 256>>>(ln_up_g, ln_up_b);

    // join on origin: p2 needs chain (in-stream) + p1 (eP1)
    cudaStreamWaitEvent(0, g_sk.eP1, 0);
    k_smooth_part<18,2,256,true,true><<<dim3(NB*HH, 2), 256, K6_SMEM>>>(smooth_b);
    k_ln_out<<<NPIX/8, 256>>>(ln_out_g, ln_out_b, out);
}